// round 11
// baseline (speedup 1.0000x reference)
#include <cuda_runtime.h>
#include <cuda_bf16.h>
#include <cstdint>

#define Bdim 32
#define Ndim 160
#define NL 25600           // 160*160
#define BC 1024            // 32*32
#define ALPHA 0.05f
#define OMA 0.95f

// ---- scratch (__device__ globals). GEMM operands stored as TWO bf16 planes
// (hi = bf16(v), lo = bf16(v - hi)); byte-neutral vs fp32. ----
__device__ __align__(16) float g_A1[Ndim*Ndim];
__device__ __align__(16) float g_A2[Ndim*Ndim];
__device__ __align__(16) __nv_bfloat16 g_Msh[2*Ndim*Ndim], g_Msl[2*Ndim*Ndim];
__device__ __align__(16) __nv_bfloat16 g_ah [Ndim*Ndim],   g_al [Ndim*Ndim];
__device__ __align__(16) __nv_bfloat16 g_Wch[64*96],       g_Wcl[64*96];
__device__ __align__(16) __nv_bfloat16 g_xh[(size_t)BC*NL],   g_xl[(size_t)BC*NL];
__device__ __align__(16) __nv_bfloat16 g_yh[(size_t)BC*2*NL], g_yl[(size_t)BC*2*NL];
__device__ __align__(16) __nv_bfloat16 g_eh[(size_t)BC*NL],   g_el[(size_t)BC*NL];
__device__ __align__(16) float g_pool[(size_t)BC*NL];

// ---------- helpers ----------
__device__ __forceinline__ uint32_t packbf(float v0, float v1) {
    uint32_t w; asm("cvt.rn.bf16x2.f32 %0, %1, %2;" : "=r"(w) : "f"(v1), "f"(v0));
    return w;
}
__device__ __forceinline__ void split_pair(float v0, float v1, uint32_t& wh, uint32_t& wl) {
    wh = packbf(v0, v1);
    float u0 = __uint_as_float(wh << 16);
    float u1 = __uint_as_float(wh & 0xFFFF0000u);
    wl = packbf(v0 - u0, v1 - u1);
}
__device__ __forceinline__ void splitb(float v, __nv_bfloat16* h, __nv_bfloat16* l) {
    __nv_bfloat16 hh = __float2bfloat16(v);
    *h = hh;
    *l = __float2bfloat16(v - __bfloat162float(hh));
}
__device__ __forceinline__ void mmabf(float* c, const uint32_t* a, const uint32_t* b) {
    asm volatile(
        "mma.sync.aligned.m16n8k16.row.col.f32.bf16.bf16.f32 "
        "{%0,%1,%2,%3}, {%4,%5,%6,%7}, {%8,%9}, {%0,%1,%2,%3};"
        : "+f"(c[0]), "+f"(c[1]), "+f"(c[2]), "+f"(c[3])
        : "r"(a[0]), "r"(a[1]), "r"(a[2]), "r"(a[3]), "r"(b[0]), "r"(b[1]));
}
__device__ __forceinline__ void ldsm4(uint32_t* r, uint32_t a) {
    asm volatile("ldmatrix.sync.aligned.m8n8.x4.shared.b16 {%0,%1,%2,%3}, [%4];"
        : "=r"(r[0]), "=r"(r[1]), "=r"(r[2]), "=r"(r[3]) : "r"(a));
}
__device__ __forceinline__ void ldsm4t(uint32_t* r, uint32_t a) {
    asm volatile("ldmatrix.sync.aligned.m8n8.x4.trans.shared.b16 {%0,%1,%2,%3}, [%4];"
        : "=r"(r[0]), "=r"(r[1]), "=r"(r[2]), "=r"(r[3]) : "r"(a));
}
__device__ __forceinline__ void ldsm2t(uint32_t* r, uint32_t a) {
    asm volatile("ldmatrix.sync.aligned.m8n8.x2.trans.shared.b16 {%0,%1}, [%2];"
        : "=r"(r[0]), "=r"(r[1]) : "r"(a));
}
__device__ __forceinline__ void cp16(uint32_t saddr, const void* gptr) {
    asm volatile("cp.async.cg.shared.global [%0], [%1], 16;" :: "r"(saddr), "l"(gptr));
}
#define CP_COMMIT() asm volatile("cp.async.commit_group;")
template<int N> __device__ __forceinline__ void cp_wait() {
    asm volatile("cp.async.wait_group %0;" :: "n"(N));
}

// ============================================================
// K1: row-normalized (a+I), (a^T+I) fp32; split copy of raw a
// ============================================================
__global__ void k_norm_adj(const float* __restrict__ a) {
    int v = blockIdx.x;
    int t = threadIdx.x;
    __shared__ float s1[Ndim], s2[Ndim];
    __shared__ float r1, r2;
    float av = a[v*Ndim + t];
    float aw = a[t*Ndim + v];
    s1[t] = av; s2[t] = aw;
    __syncthreads();
    if (t == 0) {
        float x1 = 0.f, x2 = 0.f;
        for (int i = 0; i < Ndim; i++) { x1 += s1[i]; x2 += s2[i]; }
        r1 = x1 + 1.f; r2 = x2 + 1.f;
    }
    __syncthreads();
    float diag = (t == v) ? 1.f : 0.f;
    g_A1[v*Ndim + t] = (av + diag) / r1;
    g_A2[v*Ndim + t] = (aw + diag) / r2;
    splitb(av, &g_ah[v*Ndim + t], &g_al[v*Ndim + t]);
}

// ============================================================
// K2: Mstack fp32 GEMM, split outputs into Ms planes
// ============================================================
__global__ void k_prep() {
    __shared__ float As1[32][36], As2[32][36], Bs1[32][36], Bs2[32][36];
    int tid = threadIdx.x;
    int tx = tid & 7, ty = tid >> 3;
    int bi = blockIdx.y, bj = blockIdx.x;
    float c1[4][4] = {}, c2[4][4] = {};
    for (int kt = 0; kt < 5; kt++) {
        #pragma unroll
        for (int it = 0; it < 4; it++) {
            int g = tid + it*64;
            int m = g >> 3, k4 = g & 7;
            float4 v1 = *(const float4*)&g_A1[(bi*32+m)*Ndim + kt*32 + k4*4];
            float4 v2 = *(const float4*)&g_A2[(bi*32+m)*Ndim + kt*32 + k4*4];
            As1[k4*4+0][m] = v1.x; As1[k4*4+1][m] = v1.y;
            As1[k4*4+2][m] = v1.z; As1[k4*4+3][m] = v1.w;
            As2[k4*4+0][m] = v2.x; As2[k4*4+1][m] = v2.y;
            As2[k4*4+2][m] = v2.z; As2[k4*4+3][m] = v2.w;
            int r = g >> 3, c4 = g & 7;
            *(float4*)&Bs1[r][c4*4] = *(const float4*)&g_A1[(kt*32+r)*Ndim + bj*32 + c4*4];
            *(float4*)&Bs2[r][c4*4] = *(const float4*)&g_A2[(kt*32+r)*Ndim + bj*32 + c4*4];
        }
        __syncthreads();
        #pragma unroll
        for (int k = 0; k < 32; k++) {
            float4 a1 = *(const float4*)&As1[k][ty*4];
            float4 a2 = *(const float4*)&As2[k][ty*4];
            float4 b1 = *(const float4*)&Bs1[k][tx*4];
            float4 b2 = *(const float4*)&Bs2[k][tx*4];
            float aa1[4] = {a1.x,a1.y,a1.z,a1.w}, aa2[4] = {a2.x,a2.y,a2.z,a2.w};
            float bb1[4] = {b1.x,b1.y,b1.z,b1.w}, bb2[4] = {b2.x,b2.y,b2.z,b2.w};
            #pragma unroll
            for (int i = 0; i < 4; i++)
            #pragma unroll
            for (int j = 0; j < 4; j++) {
                c1[i][j] += aa1[i]*bb1[j];
                c2[i][j] += aa2[i]*bb2[j];
            }
        }
        __syncthreads();
    }
    #pragma unroll
    for (int i = 0; i < 4; i++) {
        int row = bi*32 + ty*4 + i;
        int col = bj*32 + tx*4;
        float4 a1 = *(const float4*)&g_A1[row*Ndim + col];
        float4 a2 = *(const float4*)&g_A2[row*Ndim + col];
        float sv[4] = {a1.x+a2.x, a1.y+a2.y, a1.z+a2.z, a1.w+a2.w};
        #pragma unroll
        for (int j = 0; j < 4; j++) {
            splitb(OMA*sv[j], &g_Msh[row*Ndim + col + j], &g_Msl[row*Ndim + col + j]);
            splitb(ALPHA*OMA*sv[j] + OMA*OMA*(c1[i][j]+c2[i][j]),
                   &g_Msh[(160+row)*Ndim + col + j], &g_Msl[(160+row)*Ndim + col + j]);
        }
    }
}

// ============================================================
// K3: folded weights (split planes)
// ============================================================
__global__ void k_wcprep(const float* __restrict__ We, const float* __restrict__ Wp) {
    int idx = blockIdx.x*256 + threadIdx.x;
    if (idx >= 64*96) return;
    int o = idx / 96, k = idx % 96;
    const float* W = (o < 32) ? We : Wp;
    int oo = o & 31;
    float v;
    if (k < 32) v = 2.f*W[oo*96 + k] + 2.f*ALPHA*(W[oo*96 + k + 32] + W[oo*96 + k + 64]);
    else        v = W[oo*96 + k];
    splitb(v, &g_Wch[idx], &g_Wcl[idx]);
}

// ============================================================
// K3b: split x into planes
// ============================================================
__global__ void k_xsplit(const float* __restrict__ x) {
    size_t i4 = ((size_t)blockIdx.x*256 + threadIdx.x)*4;
    float4 v = *(const float4*)&x[i4];
    uint32_t h01, l01, h23, l23;
    split_pair(v.x, v.y, h01, l01);
    split_pair(v.z, v.w, h23, l23);
    *(uint2*)&g_xh[i4] = make_uint2(h01, h23);
    *(uint2*)&g_xl[i4] = make_uint2(l01, l23);
}

// ============================================================
// K4: batched bf16-planar GEMM (y-stage). Unchanged from R8/R9.
// ============================================================
struct TGB {
    static const int AS = 160*40;
    static const int BS = 32*88;
    static const int STGE = 2*AS + 2*BS;
    static const int SMEM = STGE*2*2;
};

__global__ void __launch_bounds__(320, 2) k_bgemm_bf(
    const __nv_bfloat16* __restrict__ Ah, const __nv_bfloat16* __restrict__ Al,
    long sA, int lda,
    const __nv_bfloat16* __restrict__ Bh, const __nv_bfloat16* __restrict__ Bl,
    long sB, int ldb,
    __nv_bfloat16* __restrict__ Coh, __nv_bfloat16* __restrict__ Col,
    long sC, int ldc)
{
    extern __shared__ __nv_bfloat16 smb[];
    const int AS = TGB::AS, STGE = TGB::STGE;
    uint32_t sb = (uint32_t)__cvta_generic_to_shared(smb);

    int bc = blockIdx.x;
    int n0 = blockIdx.y * 80;
    int m0 = blockIdx.z * 160;
    const __nv_bfloat16* Ahb = Ah + (size_t)bc*sA;
    const __nv_bfloat16* Alb = Al + (size_t)bc*sA;
    const __nv_bfloat16* Bhb = Bh + (size_t)bc*sB;
    const __nv_bfloat16* Blb = Bl + (size_t)bc*sB;

    int tid = threadIdx.x, lane = tid & 31, wid = tid >> 5;
    int wmi = wid % 5, wni = wid / 5;
    int m0w = wmi*32, n0w = wni*40;
    int g = lane >> 2, t = lane & 3;

    float acc[2][5][4] = {};

    auto stage = [&](int kt, int st) {
        uint32_t base = sb + (uint32_t)(st*STGE)*2;
        #pragma unroll
        for (int i = 0; i < 4; i++) {
            int s = tid + i*320;
            int pl = s >= 640; int ss = s - pl*640;
            int m = ss >> 2, kc = (ss & 3)*8;
            const __nv_bfloat16* src = (pl ? Alb : Ahb) + (size_t)(m0+m)*lda + kt + kc;
            cp16(base + (uint32_t)(pl*AS + m*40 + kc)*2, src);
        }
        #pragma unroll
        for (int i = 0; i < 2; i++) {
            int s = tid + i*320;
            int pl = s >= 320; int ss = s - pl*320;
            int k = ss/10, nc = (ss%10)*8;
            const __nv_bfloat16* src = (pl ? Blb : Bhb) + (size_t)(kt+k)*ldb + n0 + nc;
            cp16(base + (uint32_t)(2*AS + pl*TGB::BS + k*88 + nc)*2, src);
        }
        CP_COMMIT();
    };

    stage(0, 0);
    #pragma unroll
    for (int it = 0; it < 5; it++) {
        if (it + 1 < 5) { stage((it+1)*32, (it+1)&1); cp_wait<1>(); }
        else            { cp_wait<0>(); }
        __syncthreads();
        uint32_t sAh = sb + (uint32_t)((it&1)*STGE)*2;
        uint32_t sAl = sAh + (uint32_t)AS*2;
        uint32_t sBh = sAh + (uint32_t)(2*AS)*2;
        uint32_t sBl = sBh + (uint32_t)TGB::BS*2;
        #pragma unroll
        for (int kk = 0; kk < 32; kk += 16) {
            uint32_t Afh[2][4], Afl[2][4];
            #pragma unroll
            for (int mt = 0; mt < 2; mt++) {
                uint32_t off = (uint32_t)(((m0w + mt*16 + (lane&15))*40
                                           + kk + ((lane>>4)<<3)) << 1);
                ldsm4(Afh[mt], sAh + off);
                ldsm4(Afl[mt], sAl + off);
            }
            uint32_t Bfh[5][2], Bfl[5][2];
            int rB = kk + (lane&7) + (lane&8);
            #pragma unroll
            for (int ntp = 0; ntp < 2; ntp++) {
                uint32_t off = (uint32_t)((rB*88 + n0w + ntp*16 + ((lane>>4)<<3)) << 1);
                uint32_t rh[4], rl[4];
                ldsm4t(rh, sBh + off);
                ldsm4t(rl, sBl + off);
                Bfh[2*ntp][0]=rh[0]; Bfh[2*ntp][1]=rh[1]; Bfh[2*ntp+1][0]=rh[2]; Bfh[2*ntp+1][1]=rh[3];
                Bfl[2*ntp][0]=rl[0]; Bfl[2*ntp][1]=rl[1]; Bfl[2*ntp+1][0]=rl[2]; Bfl[2*ntp+1][1]=rl[3];
            }
            {
                uint32_t off = (uint32_t)((rB*88 + n0w + 32) << 1);
                ldsm2t(Bfh[4], sBh + off);
                ldsm2t(Bfl[4], sBl + off);
            }
            #pragma unroll
            for (int nt = 0; nt < 5; nt++)
            #pragma unroll
            for (int mt = 0; mt < 2; mt++) {
                mmabf(acc[mt][nt], Afh[mt], Bfh[nt]);
                mmabf(acc[mt][nt], Afh[mt], Bfl[nt]);
                mmabf(acc[mt][nt], Afl[mt], Bfh[nt]);
            }
        }
        __syncthreads();
    }
    #pragma unroll
    for (int mt = 0; mt < 2; mt++) {
        int r0 = m0 + m0w + mt*16 + g;
        #pragma unroll
        for (int nt = 0; nt < 5; nt++) {
            int c0 = n0 + n0w + nt*8 + 2*t;
            __nv_bfloat16* Ch = Coh + (size_t)bc*sC;
            __nv_bfloat16* Cl = Col + (size_t)bc*sC;
            uint32_t wh, wl;
            split_pair(acc[mt][nt][0], acc[mt][nt][1], wh, wl);
            *(uint32_t*)&Ch[(size_t)r0*ldc + c0] = wh;
            *(uint32_t*)&Cl[(size_t)r0*ldc + c0] = wl;
            split_pair(acc[mt][nt][2], acc[mt][nt][3], wh, wl);
            *(uint32_t*)&Ch[(size_t)(r0+8)*ldc + c0] = wh;
            *(uint32_t*)&Cl[(size_t)(r0+8)*ldc + c0] = wl;
        }
    }
}

// ============================================================
// K5: channel mix, bf16 planar (unchanged from R8/R9).
// ============================================================
#define MIXB_AS (64*40)
#define MIXB_BS (32*168)
#define MIXB_STGE (2*MIXB_AS + 2*MIXB_BS)
#define MIXB_SMEM (MIXB_STGE*2*2)

__global__ void __launch_bounds__(320, 2) k_mix_bf(
    const float* __restrict__ be, const float* __restrict__ bp)
{
    extern __shared__ __nv_bfloat16 smb[];
    uint32_t sb = (uint32_t)__cvta_generic_to_shared(smb);
    int b  = blockIdx.y;
    int p0 = blockIdx.x * 160;
    int tid = threadIdx.x, lane = tid & 31, wid = tid >> 5;
    int wmi = wid & 1, wni = wid >> 1;
    int m0w = wmi*32, n0w = wni*32;
    int g = lane >> 2, t = lane & 3;

    float acc[2][4][4] = {};

    auto stage = [&](int ktc, int st) {
        uint32_t base = sb + (uint32_t)(st*MIXB_STGE)*2;
        #pragma unroll
        for (int i = 0; i < 2; i++) {
            int s = tid + i*320;
            if (s < 512) {
                int pl = s >= 256; int ss = s & 255;
                int m = ss >> 2, kc = (ss & 3)*8;
                const __nv_bfloat16* src = (pl ? g_Wcl : g_Wch) + m*96 + ktc + kc;
                cp16(base + (uint32_t)(pl*MIXB_AS + m*40 + kc)*2, src);
            }
        }
        #pragma unroll
        for (int i = 0; i < 4; i++) {
            int s = tid + i*320;
            int pl = s >= 640; int ss = s - pl*640;
            int k = ss/20, mc = (ss%20)*8;
            int kg = ktc + k;
            int c = kg & 31;
            const __nv_bfloat16* src;
            if (pl) {
                if (kg < 32)      src = g_xl + ((size_t)b*32 + c)*NL;
                else if (kg < 64) src = g_yl + ((size_t)b*32 + c)*(2*NL);
                else              src = g_yl + ((size_t)b*32 + c)*(2*NL) + NL;
            } else {
                if (kg < 32)      src = g_xh + ((size_t)b*32 + c)*NL;
                else if (kg < 64) src = g_yh + ((size_t)b*32 + c)*(2*NL);
                else              src = g_yh + ((size_t)b*32 + c)*(2*NL) + NL;
            }
            cp16(base + (uint32_t)(2*MIXB_AS + pl*MIXB_BS + k*168 + mc)*2, src + p0 + mc);
        }
        CP_COMMIT();
    };

    stage(0, 0);
    #pragma unroll
    for (int it = 0; it < 3; it++) {
        if (it + 1 < 3) { stage((it+1)*32, (it+1)&1); cp_wait<1>(); }
        else            { cp_wait<0>(); }
        __syncthreads();
        uint32_t sAh = sb + (uint32_t)((it&1)*MIXB_STGE)*2;
        uint32_t sAl = sAh + (uint32_t)MIXB_AS*2;
        uint32_t sBh = sAh + (uint32_t)(2*MIXB_AS)*2;
        uint32_t sBl = sBh + (uint32_t)MIXB_BS*2;
        #pragma unroll
        for (int kk = 0; kk < 32; kk += 16) {
            uint32_t Afh[2][4], Afl[2][4];
            #pragma unroll
            for (int mt = 0; mt < 2; mt++) {
                uint32_t off = (uint32_t)(((m0w + mt*16 + (lane&15))*40
                                           + kk + ((lane>>4)<<3)) << 1);
                ldsm4(Afh[mt], sAh + off);
                ldsm4(Afl[mt], sAl + off);
            }
            uint32_t Bfh[4][2], Bfl[4][2];
            int rB = kk + (lane&7) + (lane&8);
            #pragma unroll
            for (int ntp = 0; ntp < 2; ntp++) {
                uint32_t off = (uint32_t)((rB*168 + n0w + ntp*16 + ((lane>>4)<<3)) << 1);
                uint32_t rh[4], rl[4];
                ldsm4t(rh, sBh + off);
                ldsm4t(rl, sBl + off);
                Bfh[2*ntp][0]=rh[0]; Bfh[2*ntp][1]=rh[1]; Bfh[2*ntp+1][0]=rh[2]; Bfh[2*ntp+1][1]=rh[3];
                Bfl[2*ntp][0]=rl[0]; Bfl[2*ntp][1]=rl[1]; Bfl[2*ntp+1][0]=rl[2]; Bfl[2*ntp+1][1]=rl[3];
            }
            #pragma unroll
            for (int nt = 0; nt < 4; nt++)
            #pragma unroll
            for (int mt = 0; mt < 2; mt++) {
                mmabf(acc[mt][nt], Afh[mt], Bfh[nt]);
                mmabf(acc[mt][nt], Afh[mt], Bfl[nt]);
                mmabf(acc[mt][nt], Afl[mt], Bfh[nt]);
            }
        }
        __syncthreads();
    }
    #pragma unroll
    for (int mt = 0; mt < 2; mt++) {
        #pragma unroll
        for (int rr = 0; rr < 2; rr++) {
            int o = m0w + mt*16 + g + rr*8;
            float bias = 2.f * ((o < 32) ? be[o] : bp[o-32]);
            int oo = o & 31;
            size_t base = ((size_t)b*32 + oo)*NL + p0;
            #pragma unroll
            for (int nt = 0; nt < 4; nt++) {
                int c0 = n0w + nt*8 + 2*t;
                float u0 = acc[mt][nt][rr*2+0] + bias;
                float u1 = acc[mt][nt][rr*2+1] + bias;
                if (o < 32) {
                    uint32_t wh, wl;
                    split_pair(u0, u1, wh, wl);
                    *(uint32_t*)&g_eh[base + c0] = wh;
                    *(uint32_t*)&g_el[base + c0] = wl;
                } else {
                    *(float2*)&g_pool[base + c0] = make_float2(u0, u1);
                }
            }
        }
    }
}

// ============================================================
// K7: FUSED epilogue (R9 structure) + IN-KERNEL SOFTMAX.
//   prologue: cp.async pool fp32 -> smem P (overlays ring+t, dead until ph0);
//             2-thread/column online softmax -> s planes in smem.
//   phase0: x_new = s^T e (e streamed, 3-slot ring)
//   phase1: t = s a (a streamed, t -> smem planes)
//   phase2: a_new = t s (all smem)
// smem elems(bf16): s_h@0, s_l@26880, t_h@53760, t_l@67200, ring@80640 (3x10752).
// P (pool fp32 [160][164]) at byte 107520..212480 (overlays t+ring region).
// ============================================================
#define EPI_SL     26880
#define EPI_TH     53760
#define EPI_TL     67200
#define EPI_STG    80640
#define EPI_STG_PL 5376
#define EPI_STG_ST 10752
#define EPI_PBYTE  107520
#define EPI_SMEM   (112896*2)

__device__ __forceinline__ void frag_mma_row(
    float (&acc)[10][4], const uint32_t* Ah, const uint32_t* Al,
    uint32_t sBh, uint32_t sBl, int rB, int ldb, int n0w, int lane)
{
    #pragma unroll
    for (int ntp = 0; ntp < 5; ntp++) {
        uint32_t off = (uint32_t)((rB*ldb + n0w + ntp*16 + ((lane>>4)<<3)) << 1);
        uint32_t rh[4], rl[4];
        ldsm4t(rh, sBh + off);
        ldsm4t(rl, sBl + off);
        uint32_t bh0[2] = {rh[0], rh[1]}, bh1[2] = {rh[2], rh[3]};
        uint32_t bl0[2] = {rl[0], rl[1]}, bl1[2] = {rl[2], rl[3]};
        mmabf(acc[2*ntp],   Ah, bh0);
        mmabf(acc[2*ntp],   Ah, bl0);
        mmabf(acc[2*ntp],   Al, bh0);
        mmabf(acc[2*ntp+1], Ah, bh1);
        mmabf(acc[2*ntp+1], Ah, bl1);
        mmabf(acc[2*ntp+1], Al, bh1);
    }
}

__global__ void __launch_bounds__(320, 1) k_epi(
    float* __restrict__ xnew, float* __restrict__ anew)
{
    extern __shared__ __nv_bfloat16 smb[];
    uint32_t sb = (uint32_t)__cvta_generic_to_shared(smb);
    int bc = blockIdx.x;
    int h  = blockIdx.y;                  // 0/1: which 80-row half
    int tid = threadIdx.x, lane = tid & 31, wid = tid >> 5;
    int wmi = wid % 5, wni = wid / 5;
    int g = lane >> 2, t4 = lane & 3;
    int m0 = h*80 + wmi*16;
    int n0w = wni*80;

    const __nv_bfloat16* eh_g = g_eh + (size_t)bc*NL;
    const __nv_bfloat16* el_g = g_el + (size_t)bc*NL;
    const float* pool_g = g_pool + (size_t)bc*NL;
    float* Pf = (float*)((char*)smb + EPI_PBYTE);   // [160][164]

    // ---- prologue: async-load pool fp32 ----
    #pragma unroll
    for (int i = 0; i < 20; i++) {
        int s = tid + i*320;              // 6400 cp16
        int n = s/40, c4 = (s%40)*4;
        cp16(sb + (uint32_t)(EPI_PBYTE + (n*164 + c4)*4), &pool_g[n*160 + c4]);
    }
    CP_COMMIT();
    cp_wait<0>();
    __syncthreads();

    // ---- in-kernel softmax over node axis (2 threads per column) ----
    {
        int l = tid % 160, hf = tid / 160;
        float m = -3.4e38f, d = 0.f;
        #pragma unroll 4
        for (int n = hf*80; n < hf*80 + 80; n++) {
            float v = Pf[n*164 + l];
            float m2 = fmaxf(m, v);
            d = d * __expf(m - m2) + __expf(v - m2);
            m = m2;
        }
        Pf[l*164 + 160 + hf] = m;
        Pf[l*164 + 162 + hf] = d;
        __syncthreads();
        float m0v = Pf[l*164 + 160], m1v = Pf[l*164 + 161];
        float d0 = Pf[l*164 + 162], d1 = Pf[l*164 + 163];
        float mm = fmaxf(m0v, m1v);
        float dd = d0*__expf(m0v - mm) + d1*__expf(m1v - mm);
        float inv = 1.f / dd;
        #pragma unroll 4
        for (int n = hf*80; n < hf*80 + 80; n++) {
            float v = __expf(Pf[n*164 + l] - mm) * inv;
            splitb(v, smb + n*168 + l, smb + EPI_SL + n*168 + l);
        }
    }
    __syncthreads();

    auto stage = [&](const __nv_bfloat16* bh, const __nv_bfloat16* bl,
                     int ch, int slot) {
        uint32_t base = sb + (uint32_t)(EPI_STG + slot*EPI_STG_ST)*2;
        #pragma unroll
        for (int i = 0; i < 4; i++) {
            int s = tid + i*320;
            int pl = s >= 640; int ss = s - pl*640;
            int r = ss/20, c8 = (ss%20)*8;
            const __nv_bfloat16* src = (pl ? bl : bh) + (ch*32 + r)*160 + c8;
            cp16(base + (uint32_t)(pl*EPI_STG_PL + r*168 + c8)*2, src);
        }
        CP_COMMIT();
    };

    float acc[10][4];

    // ================= phase 0: x_new = s^T @ e =================
    #pragma unroll
    for (int i = 0; i < 10; i++)
        acc[i][0] = acc[i][1] = acc[i][2] = acc[i][3] = 0.f;
    stage(eh_g, el_g, 0, 0);
    stage(eh_g, el_g, 1, 1);
    for (int ch = 0; ch < 5; ch++) {
        if (ch + 2 < 5) stage(eh_g, el_g, ch+2, (ch+2)%3); else CP_COMMIT();
        cp_wait<2>();
        __syncthreads();
        uint32_t stb  = sb + (uint32_t)(EPI_STG + (ch%3)*EPI_STG_ST)*2;
        uint32_t stbl = stb + (uint32_t)EPI_STG_PL*2;
        #pragma unroll
        for (int kk = 0; kk < 32; kk += 16) {
            int kg = ch*32 + kk;
            uint32_t Ah[4], Al[4];
            uint32_t offA = (uint32_t)(((kg + (lane&7) + ((lane>>4)<<3))*168
                                        + m0 + (lane&8)) << 1);
            ldsm4t(Ah, sb + offA);
            ldsm4t(Al, sb + (uint32_t)(EPI_SL*2) + offA);
            int rB = kk + (lane&7) + (lane&8);
            frag_mma_row(acc, Ah, Al, stb, stbl, rB, 168, n0w, lane);
        }
        __syncthreads();
    }
    {
        float* X = xnew + (size_t)bc*NL;
        int r0 = m0 + g;
        #pragma unroll
        for (int nt = 0; nt < 10; nt++) {
            int c0 = n0w + nt*8 + 2*t4;
            *(float2*)&X[(size_t)r0*160 + c0]     = make_float2(acc[nt][0], acc[nt][1]);
            *(float2*)&X[(size_t)(r0+8)*160 + c0] = make_float2(acc[nt][2], acc[nt][3]);
        }
    }

    // ================= phase 1: t = s @ a (t -> smem) =================
    #pragma unroll
    for (int i = 0; i < 10; i++)
        acc[i][0] = acc[i][1] = acc[i][2] = acc[i][3] = 0.f;
    stage(g_ah, g_al, 0, 0);
    stage(g_ah, g_al, 1, 1);
    for (int ch = 0; ch < 5; ch++) {
        if (ch + 2 < 5) stage(g_ah, g_al, ch+2, (ch+2)%3); else CP_COMMIT();
        cp_wait<2>();
        __syncthreads();
        uint32_t stb  = sb + (uint32_t)(EPI_STG + (ch%3)*EPI_STG_ST)*2;
        uint32_t stbl = stb + (uint32_t)EPI_STG_PL*2;
        #pragma unroll
        for (int kk = 0; kk < 32; kk += 16) {
            int kg = ch*32 + kk;
            uint32_t Ah[4], Al[4];
            uint32_t offA = (uint32_t)(((m0 + (lane&15))*168
                                        + kg + ((lane>>4)<<3)) << 1);
            ldsm4(Ah, sb + offA);
            ldsm4(Al, sb + (uint32_t)(EPI_SL*2) + offA);
            int rB = kk + (lane&7) + (lane&8);
            frag_mma_row(acc, Ah, Al, stb, stbl, rB, 168, n0w, lane);
        }
        __syncthreads();
    }
    {   // split t into smem planes
        int r0l = wmi*16 + g;
        #pragma unroll
        for (int nt = 0; nt < 10; nt++) {
            int c0 = n0w + nt*8 + 2*t4;
            uint32_t wh, wl;
            split_pair(acc[nt][0], acc[nt][1], wh, wl);
            *(uint32_t*)(smb + EPI_TH + r0l*168 + c0) = wh;
            *(uint32_t*)(smb + EPI_TL + r0l*168 + c0) = wl;
            split_pair(acc[nt][2], acc[nt][3], wh, wl);
            *(uint32_t*)(smb + EPI_TH + (r0l+8)*168 + c0) = wh;
            *(uint32_t*)(smb + EPI_TL + (r0l+8)*168 + c0) = wl;
        }
    }
    __syncthreads();

    // ================= phase 2: a_new = t @ s (all smem) =================
    #pragma unroll
    for (int i = 0; i < 10; i++)
        acc[i][0] = acc[i][1] = acc[i][2] = acc[i][3] = 0.f;
    #pragma unroll
    for (int k16 = 0; k16 < 10; k16++) {
        int kg = k16*16;
        uint32_t Ah[4], Al[4];
        uint32_t offA = (uint32_t)(((wmi*16 + (lane&15))*168
                                    + kg + ((lane>>4)<<3)) << 1);
        ldsm4(Ah, sb + (uint32_t)(EPI_TH*2) + offA);
        ldsm4(Al, sb + (uint32_t)(EPI_TL*2) + offA);
        int rB = kg + (lane&7) + (lane&8);
        frag_mma_row(acc, Ah, Al, sb, sb + (uint32_t)(EPI_SL*2), rB, 168, n0w, lane);
    }
    {
        float* Aout = anew + (size_t)bc*NL;
        int r0 = m0 + g;
        #pragma unroll
        for (int nt = 0; nt < 10; nt++) {
            int c0 = n0w + nt*8 + 2*t4;
            *(float2*)&Aout[(size_t)r0*160 + c0]     = make_float2(acc[nt][0], acc[nt][1]);
            *(float2*)&Aout[(size_t)(r0+8)*160 + c0] = make_float2(acc[nt][2], acc[nt][3]);
        }
    }
}

// ============================================================
extern "C" void kernel_launch(void* const* d_in, const int* in_sizes, int n_in,
                              void* d_out, int out_size) {
    const float* x  = (const float*)d_in[0];
    const float* a  = (const float*)d_in[1];
    const float* We = (const float*)d_in[2];
    const float* be = (const float*)d_in[3];
    const float* Wp = (const float*)d_in[4];
    const float* bp = (const float*)d_in[5];
    float* out  = (float*)d_out;
    float* xnew = out;
    float* anew = out + (size_t)BC*NL;

    void *pMsh, *pMsl, *pxh, *pxl, *pyh, *pyl;
    cudaGetSymbolAddress(&pMsh, g_Msh); cudaGetSymbolAddress(&pMsl, g_Msl);
    cudaGetSymbolAddress(&pxh,  g_xh);  cudaGetSymbolAddress(&pxl,  g_xl);
    cudaGetSymbolAddress(&pyh,  g_yh);  cudaGetSymbolAddress(&pyl,  g_yl);

    cudaFuncSetAttribute((const void*)k_bgemm_bf,
        cudaFuncAttributeMaxDynamicSharedMemorySize, TGB::SMEM);
    cudaFuncSetAttribute((const void*)k_mix_bf,
        cudaFuncAttributeMaxDynamicSharedMemorySize, MIXB_SMEM);
    cudaFuncSetAttribute((const void*)k_epi,
        cudaFuncAttributeMaxDynamicSharedMemorySize, EPI_SMEM);

    k_norm_adj<<<Ndim, Ndim>>>(a);
    k_prep<<<dim3(5, 5), 64>>>();
    k_wcprep<<<(64*96 + 255)/256, 256>>>(We, Wp);
    k_xsplit<<<(int)(((size_t)BC*NL)/1024), 256>>>(x);

    // ystack = Ms @ x : A shared (sA=0), B = x planes, C = y planes (split)
    k_bgemm_bf<<<dim3(BC, 2, 2), 320, TGB::SMEM>>>(
        (const __nv_bfloat16*)pMsh, (const __nv_bfloat16*)pMsl, 0, Ndim,
        (const __nv_bfloat16*)pxh,  (const __nv_bfloat16*)pxl,  NL, Ndim,
        (__nv_bfloat16*)pyh, (__nv_bfloat16*)pyl, 2*NL, Ndim);

    // channel mix -> embed (split planes), pool (fp32)
    k_mix_bf<<<dim3(NL/160, Bdim), 320, MIXB_SMEM>>>(be, bp);

    // fused: softmax(pool) ; x_new = s^T e ; t = s a ; a_new = t s
    k_epi<<<dim3(BC, 2), 320, EPI_SMEM>>>(xnew, anew);
}

// round 13
// speedup vs baseline: 1.0626x; 1.0626x over previous
#include <cuda_runtime.h>
#include <cuda_bf16.h>
#include <cstdint>

#define Bdim 32
#define Ndim 160
#define NL 25600           // 160*160
#define BC 1024            // 32*32
#define ALPHA 0.05f
#define OMA 0.95f

// ---- scratch (__device__ globals). GEMM operands stored as TWO bf16 planes
// (hi = bf16(v), lo = bf16(v - hi)); byte-neutral vs fp32. ----
__device__ __align__(16) float g_A1[Ndim*Ndim];
__device__ __align__(16) float g_A2[Ndim*Ndim];
__device__ __align__(16) __nv_bfloat16 g_Msh[2*Ndim*Ndim], g_Msl[2*Ndim*Ndim];
__device__ __align__(16) __nv_bfloat16 g_ah [Ndim*Ndim],   g_al [Ndim*Ndim];
__device__ __align__(16) __nv_bfloat16 g_Wch[64*96],       g_Wcl[64*96];
__device__ __align__(16) __nv_bfloat16 g_xh[(size_t)BC*NL],   g_xl[(size_t)BC*NL];
__device__ __align__(16) __nv_bfloat16 g_yh[(size_t)BC*2*NL], g_yl[(size_t)BC*2*NL];
__device__ __align__(16) __nv_bfloat16 g_eh[(size_t)BC*NL],   g_el[(size_t)BC*NL];
__device__ __align__(16) float g_pool[(size_t)BC*NL];
__device__ __align__(16) __nv_bfloat16 g_sh[(size_t)BC*NL],   g_sl[(size_t)BC*NL];

// ---------- helpers ----------
__device__ __forceinline__ uint32_t packbf(float v0, float v1) {
    uint32_t w; asm("cvt.rn.bf16x2.f32 %0, %1, %2;" : "=r"(w) : "f"(v1), "f"(v0));
    return w;
}
__device__ __forceinline__ void split_pair(float v0, float v1, uint32_t& wh, uint32_t& wl) {
    wh = packbf(v0, v1);
    float u0 = __uint_as_float(wh << 16);
    float u1 = __uint_as_float(wh & 0xFFFF0000u);
    wl = packbf(v0 - u0, v1 - u1);
}
__device__ __forceinline__ void splitb(float v, __nv_bfloat16* h, __nv_bfloat16* l) {
    __nv_bfloat16 hh = __float2bfloat16(v);
    *h = hh;
    *l = __float2bfloat16(v - __bfloat162float(hh));
}
__device__ __forceinline__ void mmabf(float* c, const uint32_t* a, const uint32_t* b) {
    asm volatile(
        "mma.sync.aligned.m16n8k16.row.col.f32.bf16.bf16.f32 "
        "{%0,%1,%2,%3}, {%4,%5,%6,%7}, {%8,%9}, {%0,%1,%2,%3};"
        : "+f"(c[0]), "+f"(c[1]), "+f"(c[2]), "+f"(c[3])
        : "r"(a[0]), "r"(a[1]), "r"(a[2]), "r"(a[3]), "r"(b[0]), "r"(b[1]));
}
__device__ __forceinline__ void ldsm4(uint32_t* r, uint32_t a) {
    asm volatile("ldmatrix.sync.aligned.m8n8.x4.shared.b16 {%0,%1,%2,%3}, [%4];"
        : "=r"(r[0]), "=r"(r[1]), "=r"(r[2]), "=r"(r[3]) : "r"(a));
}
__device__ __forceinline__ void ldsm4t(uint32_t* r, uint32_t a) {
    asm volatile("ldmatrix.sync.aligned.m8n8.x4.trans.shared.b16 {%0,%1,%2,%3}, [%4];"
        : "=r"(r[0]), "=r"(r[1]), "=r"(r[2]), "=r"(r[3]) : "r"(a));
}
__device__ __forceinline__ void ldsm2t(uint32_t* r, uint32_t a) {
    asm volatile("ldmatrix.sync.aligned.m8n8.x2.trans.shared.b16 {%0,%1}, [%2];"
        : "=r"(r[0]), "=r"(r[1]) : "r"(a));
}
__device__ __forceinline__ void cp16(uint32_t saddr, const void* gptr) {
    asm volatile("cp.async.cg.shared.global [%0], [%1], 16;" :: "r"(saddr), "l"(gptr));
}
#define CP_COMMIT() asm volatile("cp.async.commit_group;")
template<int N> __device__ __forceinline__ void cp_wait() {
    asm volatile("cp.async.wait_group %0;" :: "n"(N));
}

// ============================================================
// K1: row-normalized (a+I), (a^T+I) fp32; split copy of raw a
// ============================================================
__global__ void k_norm_adj(const float* __restrict__ a) {
    int v = blockIdx.x;
    int t = threadIdx.x;
    __shared__ float s1[Ndim], s2[Ndim];
    __shared__ float r1, r2;
    float av = a[v*Ndim + t];
    float aw = a[t*Ndim + v];
    s1[t] = av; s2[t] = aw;
    __syncthreads();
    if (t == 0) {
        float x1 = 0.f, x2 = 0.f;
        for (int i = 0; i < Ndim; i++) { x1 += s1[i]; x2 += s2[i]; }
        r1 = x1 + 1.f; r2 = x2 + 1.f;
    }
    __syncthreads();
    float diag = (t == v) ? 1.f : 0.f;
    g_A1[v*Ndim + t] = (av + diag) / r1;
    g_A2[v*Ndim + t] = (aw + diag) / r2;
    splitb(av, &g_ah[v*Ndim + t], &g_al[v*Ndim + t]);
}

// ============================================================
// K2: Mstack fp32 GEMM, split outputs into Ms planes
// ============================================================
__global__ void k_prep() {
    __shared__ float As1[32][36], As2[32][36], Bs1[32][36], Bs2[32][36];
    int tid = threadIdx.x;
    int tx = tid & 7, ty = tid >> 3;
    int bi = blockIdx.y, bj = blockIdx.x;
    float c1[4][4] = {}, c2[4][4] = {};
    for (int kt = 0; kt < 5; kt++) {
        #pragma unroll
        for (int it = 0; it < 4; it++) {
            int g = tid + it*64;
            int m = g >> 3, k4 = g & 7;
            float4 v1 = *(const float4*)&g_A1[(bi*32+m)*Ndim + kt*32 + k4*4];
            float4 v2 = *(const float4*)&g_A2[(bi*32+m)*Ndim + kt*32 + k4*4];
            As1[k4*4+0][m] = v1.x; As1[k4*4+1][m] = v1.y;
            As1[k4*4+2][m] = v1.z; As1[k4*4+3][m] = v1.w;
            As2[k4*4+0][m] = v2.x; As2[k4*4+1][m] = v2.y;
            As2[k4*4+2][m] = v2.z; As2[k4*4+3][m] = v2.w;
            int r = g >> 3, c4 = g & 7;
            *(float4*)&Bs1[r][c4*4] = *(const float4*)&g_A1[(kt*32+r)*Ndim + bj*32 + c4*4];
            *(float4*)&Bs2[r][c4*4] = *(const float4*)&g_A2[(kt*32+r)*Ndim + bj*32 + c4*4];
        }
        __syncthreads();
        #pragma unroll
        for (int k = 0; k < 32; k++) {
            float4 a1 = *(const float4*)&As1[k][ty*4];
            float4 a2 = *(const float4*)&As2[k][ty*4];
            float4 b1 = *(const float4*)&Bs1[k][tx*4];
            float4 b2 = *(const float4*)&Bs2[k][tx*4];
            float aa1[4] = {a1.x,a1.y,a1.z,a1.w}, aa2[4] = {a2.x,a2.y,a2.z,a2.w};
            float bb1[4] = {b1.x,b1.y,b1.z,b1.w}, bb2[4] = {b2.x,b2.y,b2.z,b2.w};
            #pragma unroll
            for (int i = 0; i < 4; i++)
            #pragma unroll
            for (int j = 0; j < 4; j++) {
                c1[i][j] += aa1[i]*bb1[j];
                c2[i][j] += aa2[i]*bb2[j];
            }
        }
        __syncthreads();
    }
    #pragma unroll
    for (int i = 0; i < 4; i++) {
        int row = bi*32 + ty*4 + i;
        int col = bj*32 + tx*4;
        float4 a1 = *(const float4*)&g_A1[row*Ndim + col];
        float4 a2 = *(const float4*)&g_A2[row*Ndim + col];
        float sv[4] = {a1.x+a2.x, a1.y+a2.y, a1.z+a2.z, a1.w+a2.w};
        #pragma unroll
        for (int j = 0; j < 4; j++) {
            splitb(OMA*sv[j], &g_Msh[row*Ndim + col + j], &g_Msl[row*Ndim + col + j]);
            splitb(ALPHA*OMA*sv[j] + OMA*OMA*(c1[i][j]+c2[i][j]),
                   &g_Msh[(160+row)*Ndim + col + j], &g_Msl[(160+row)*Ndim + col + j]);
        }
    }
}

// ============================================================
// K3: folded weights (split planes)
// ============================================================
__global__ void k_wcprep(const float* __restrict__ We, const float* __restrict__ Wp) {
    int idx = blockIdx.x*256 + threadIdx.x;
    if (idx >= 64*96) return;
    int o = idx / 96, k = idx % 96;
    const float* W = (o < 32) ? We : Wp;
    int oo = o & 31;
    float v;
    if (k < 32) v = 2.f*W[oo*96 + k] + 2.f*ALPHA*(W[oo*96 + k + 32] + W[oo*96 + k + 64]);
    else        v = W[oo*96 + k];
    splitb(v, &g_Wch[idx], &g_Wcl[idx]);
}

// ============================================================
// K3b: split x into planes
// ============================================================
__global__ void k_xsplit(const float* __restrict__ x) {
    size_t i4 = ((size_t)blockIdx.x*256 + threadIdx.x)*4;
    float4 v = *(const float4*)&x[i4];
    uint32_t h01, l01, h23, l23;
    split_pair(v.x, v.y, h01, l01);
    split_pair(v.z, v.w, h23, l23);
    *(uint2*)&g_xh[i4] = make_uint2(h01, h23);
    *(uint2*)&g_xl[i4] = make_uint2(l01, l23);
}

// ============================================================
// K4: batched bf16-planar GEMM (y-stage). Unchanged from R8/R9.
// ============================================================
struct TGB {
    static const int AS = 160*40;
    static const int BS = 32*88;
    static const int STGE = 2*AS + 2*BS;
    static const int SMEM = STGE*2*2;
};

__global__ void __launch_bounds__(320, 2) k_bgemm_bf(
    const __nv_bfloat16* __restrict__ Ah, const __nv_bfloat16* __restrict__ Al,
    long sA, int lda,
    const __nv_bfloat16* __restrict__ Bh, const __nv_bfloat16* __restrict__ Bl,
    long sB, int ldb,
    __nv_bfloat16* __restrict__ Coh, __nv_bfloat16* __restrict__ Col,
    long sC, int ldc)
{
    extern __shared__ __nv_bfloat16 smb[];
    const int AS = TGB::AS, STGE = TGB::STGE;
    uint32_t sb = (uint32_t)__cvta_generic_to_shared(smb);

    int bc = blockIdx.x;
    int n0 = blockIdx.y * 80;
    int m0 = blockIdx.z * 160;
    const __nv_bfloat16* Ahb = Ah + (size_t)bc*sA;
    const __nv_bfloat16* Alb = Al + (size_t)bc*sA;
    const __nv_bfloat16* Bhb = Bh + (size_t)bc*sB;
    const __nv_bfloat16* Blb = Bl + (size_t)bc*sB;

    int tid = threadIdx.x, lane = tid & 31, wid = tid >> 5;
    int wmi = wid % 5, wni = wid / 5;
    int m0w = wmi*32, n0w = wni*40;
    int g = lane >> 2, t = lane & 3;

    float acc[2][5][4] = {};

    auto stage = [&](int kt, int st) {
        uint32_t base = sb + (uint32_t)(st*STGE)*2;
        #pragma unroll
        for (int i = 0; i < 4; i++) {
            int s = tid + i*320;
            int pl = s >= 640; int ss = s - pl*640;
            int m = ss >> 2, kc = (ss & 3)*8;
            const __nv_bfloat16* src = (pl ? Alb : Ahb) + (size_t)(m0+m)*lda + kt + kc;
            cp16(base + (uint32_t)(pl*AS + m*40 + kc)*2, src);
        }
        #pragma unroll
        for (int i = 0; i < 2; i++) {
            int s = tid + i*320;
            int pl = s >= 320; int ss = s - pl*320;
            int k = ss/10, nc = (ss%10)*8;
            const __nv_bfloat16* src = (pl ? Blb : Bhb) + (size_t)(kt+k)*ldb + n0 + nc;
            cp16(base + (uint32_t)(2*AS + pl*TGB::BS + k*88 + nc)*2, src);
        }
        CP_COMMIT();
    };

    stage(0, 0);
    #pragma unroll
    for (int it = 0; it < 5; it++) {
        if (it + 1 < 5) { stage((it+1)*32, (it+1)&1); cp_wait<1>(); }
        else            { cp_wait<0>(); }
        __syncthreads();
        uint32_t sAh = sb + (uint32_t)((it&1)*STGE)*2;
        uint32_t sAl = sAh + (uint32_t)AS*2;
        uint32_t sBh = sAh + (uint32_t)(2*AS)*2;
        uint32_t sBl = sBh + (uint32_t)TGB::BS*2;
        #pragma unroll
        for (int kk = 0; kk < 32; kk += 16) {
            uint32_t Afh[2][4], Afl[2][4];
            #pragma unroll
            for (int mt = 0; mt < 2; mt++) {
                uint32_t off = (uint32_t)(((m0w + mt*16 + (lane&15))*40
                                           + kk + ((lane>>4)<<3)) << 1);
                ldsm4(Afh[mt], sAh + off);
                ldsm4(Afl[mt], sAl + off);
            }
            uint32_t Bfh[5][2], Bfl[5][2];
            int rB = kk + (lane&7) + (lane&8);
            #pragma unroll
            for (int ntp = 0; ntp < 2; ntp++) {
                uint32_t off = (uint32_t)((rB*88 + n0w + ntp*16 + ((lane>>4)<<3)) << 1);
                uint32_t rh[4], rl[4];
                ldsm4t(rh, sBh + off);
                ldsm4t(rl, sBl + off);
                Bfh[2*ntp][0]=rh[0]; Bfh[2*ntp][1]=rh[1]; Bfh[2*ntp+1][0]=rh[2]; Bfh[2*ntp+1][1]=rh[3];
                Bfl[2*ntp][0]=rl[0]; Bfl[2*ntp][1]=rl[1]; Bfl[2*ntp+1][0]=rl[2]; Bfl[2*ntp+1][1]=rl[3];
            }
            {
                uint32_t off = (uint32_t)((rB*88 + n0w + 32) << 1);
                ldsm2t(Bfh[4], sBh + off);
                ldsm2t(Bfl[4], sBl + off);
            }
            #pragma unroll
            for (int nt = 0; nt < 5; nt++)
            #pragma unroll
            for (int mt = 0; mt < 2; mt++) {
                mmabf(acc[mt][nt], Afh[mt], Bfh[nt]);
                mmabf(acc[mt][nt], Afh[mt], Bfl[nt]);
                mmabf(acc[mt][nt], Afl[mt], Bfh[nt]);
            }
        }
        __syncthreads();
    }
    #pragma unroll
    for (int mt = 0; mt < 2; mt++) {
        int r0 = m0 + m0w + mt*16 + g;
        #pragma unroll
        for (int nt = 0; nt < 5; nt++) {
            int c0 = n0 + n0w + nt*8 + 2*t;
            __nv_bfloat16* Ch = Coh + (size_t)bc*sC;
            __nv_bfloat16* Cl = Col + (size_t)bc*sC;
            uint32_t wh, wl;
            split_pair(acc[mt][nt][0], acc[mt][nt][1], wh, wl);
            *(uint32_t*)&Ch[(size_t)r0*ldc + c0] = wh;
            *(uint32_t*)&Cl[(size_t)r0*ldc + c0] = wl;
            split_pair(acc[mt][nt][2], acc[mt][nt][3], wh, wl);
            *(uint32_t*)&Ch[(size_t)(r0+8)*ldc + c0] = wh;
            *(uint32_t*)&Cl[(size_t)(r0+8)*ldc + c0] = wl;
        }
    }
}

// ============================================================
// K5: channel mix, bf16 planar (unchanged from R8/R9).
// ============================================================
#define MIXB_AS (64*40)
#define MIXB_BS (32*168)
#define MIXB_STGE (2*MIXB_AS + 2*MIXB_BS)
#define MIXB_SMEM (MIXB_STGE*2*2)

__global__ void __launch_bounds__(320, 2) k_mix_bf(
    const float* __restrict__ be, const float* __restrict__ bp)
{
    extern __shared__ __nv_bfloat16 smb[];
    uint32_t sb = (uint32_t)__cvta_generic_to_shared(smb);
    int b  = blockIdx.y;
    int p0 = blockIdx.x * 160;
    int tid = threadIdx.x, lane = tid & 31, wid = tid >> 5;
    int wmi = wid & 1, wni = wid >> 1;
    int m0w = wmi*32, n0w = wni*32;
    int g = lane >> 2, t = lane & 3;

    float acc[2][4][4] = {};

    auto stage = [&](int ktc, int st) {
        uint32_t base = sb + (uint32_t)(st*MIXB_STGE)*2;
        #pragma unroll
        for (int i = 0; i < 2; i++) {
            int s = tid + i*320;
            if (s < 512) {
                int pl = s >= 256; int ss = s & 255;
                int m = ss >> 2, kc = (ss & 3)*8;
                const __nv_bfloat16* src = (pl ? g_Wcl : g_Wch) + m*96 + ktc + kc;
                cp16(base + (uint32_t)(pl*MIXB_AS + m*40 + kc)*2, src);
            }
        }
        #pragma unroll
        for (int i = 0; i < 4; i++) {
            int s = tid + i*320;
            int pl = s >= 640; int ss = s - pl*640;
            int k = ss/20, mc = (ss%20)*8;
            int kg = ktc + k;
            int c = kg & 31;
            const __nv_bfloat16* src;
            if (pl) {
                if (kg < 32)      src = g_xl + ((size_t)b*32 + c)*NL;
                else if (kg < 64) src = g_yl + ((size_t)b*32 + c)*(2*NL);
                else              src = g_yl + ((size_t)b*32 + c)*(2*NL) + NL;
            } else {
                if (kg < 32)      src = g_xh + ((size_t)b*32 + c)*NL;
                else if (kg < 64) src = g_yh + ((size_t)b*32 + c)*(2*NL);
                else              src = g_yh + ((size_t)b*32 + c)*(2*NL) + NL;
            }
            cp16(base + (uint32_t)(2*MIXB_AS + pl*MIXB_BS + k*168 + mc)*2, src + p0 + mc);
        }
        CP_COMMIT();
    };

    stage(0, 0);
    #pragma unroll
    for (int it = 0; it < 3; it++) {
        if (it + 1 < 3) { stage((it+1)*32, (it+1)&1); cp_wait<1>(); }
        else            { cp_wait<0>(); }
        __syncthreads();
        uint32_t sAh = sb + (uint32_t)((it&1)*MIXB_STGE)*2;
        uint32_t sAl = sAh + (uint32_t)MIXB_AS*2;
        uint32_t sBh = sAh + (uint32_t)(2*MIXB_AS)*2;
        uint32_t sBl = sBh + (uint32_t)MIXB_BS*2;
        #pragma unroll
        for (int kk = 0; kk < 32; kk += 16) {
            uint32_t Afh[2][4], Afl[2][4];
            #pragma unroll
            for (int mt = 0; mt < 2; mt++) {
                uint32_t off = (uint32_t)(((m0w + mt*16 + (lane&15))*40
                                           + kk + ((lane>>4)<<3)) << 1);
                ldsm4(Afh[mt], sAh + off);
                ldsm4(Afl[mt], sAl + off);
            }
            uint32_t Bfh[4][2], Bfl[4][2];
            int rB = kk + (lane&7) + (lane&8);
            #pragma unroll
            for (int ntp = 0; ntp < 2; ntp++) {
                uint32_t off = (uint32_t)((rB*168 + n0w + ntp*16 + ((lane>>4)<<3)) << 1);
                uint32_t rh[4], rl[4];
                ldsm4t(rh, sBh + off);
                ldsm4t(rl, sBl + off);
                Bfh[2*ntp][0]=rh[0]; Bfh[2*ntp][1]=rh[1]; Bfh[2*ntp+1][0]=rh[2]; Bfh[2*ntp+1][1]=rh[3];
                Bfl[2*ntp][0]=rl[0]; Bfl[2*ntp][1]=rl[1]; Bfl[2*ntp+1][0]=rl[2]; Bfl[2*ntp+1][1]=rl[3];
            }
            #pragma unroll
            for (int nt = 0; nt < 4; nt++)
            #pragma unroll
            for (int mt = 0; mt < 2; mt++) {
                mmabf(acc[mt][nt], Afh[mt], Bfh[nt]);
                mmabf(acc[mt][nt], Afh[mt], Bfl[nt]);
                mmabf(acc[mt][nt], Afl[mt], Bfh[nt]);
            }
        }
        __syncthreads();
    }
    #pragma unroll
    for (int mt = 0; mt < 2; mt++) {
        #pragma unroll
        for (int rr = 0; rr < 2; rr++) {
            int o = m0w + mt*16 + g + rr*8;
            float bias = 2.f * ((o < 32) ? be[o] : bp[o-32]);
            int oo = o & 31;
            size_t base = ((size_t)b*32 + oo)*NL + p0;
            #pragma unroll
            for (int nt = 0; nt < 4; nt++) {
                int c0 = n0w + nt*8 + 2*t;
                float u0 = acc[mt][nt][rr*2+0] + bias;
                float u1 = acc[mt][nt][rr*2+1] + bias;
                if (o < 32) {
                    uint32_t wh, wl;
                    split_pair(u0, u1, wh, wl);
                    *(uint32_t*)&g_eh[base + c0] = wh;
                    *(uint32_t*)&g_el[base + c0] = wl;
                } else {
                    *(float2*)&g_pool[base + c0] = make_float2(u0, u1);
                }
            }
        }
    }
}

// ============================================================
// K6: softmax over node axis; split bf16 planar output
// ============================================================
#define SMAX_SMEM (160*161*4)
__global__ void k_softmax3() {
    extern __shared__ float sp[];
    int bc = blockIdx.x;
    int l = threadIdx.x;
    const float* p = g_pool + (size_t)bc*NL;
    for (int n = 0; n < Ndim; n++)
        sp[n*161 + l] = p[n*Ndim + l];
    __syncthreads();
    float m = -3.4e38f, d = 0.f;
    #pragma unroll 4
    for (int n = 0; n < Ndim; n++) {
        float v = sp[n*161 + l];
        float m2 = fmaxf(m, v);
        d = d * __expf(m - m2) + __expf(v - m2);
        m = m2;
    }
    float inv = 1.f / d;
    __nv_bfloat16* sh = g_sh + (size_t)bc*NL;
    __nv_bfloat16* sl = g_sl + (size_t)bc*NL;
    #pragma unroll 4
    for (int n = 0; n < Ndim; n++) {
        float v = __expf(sp[n*161 + l] - m) * inv;
        splitb(v, &sh[n*Ndim + l], &sl[n*Ndim + l]);
    }
}

// ---- shared B-fragment mma helper (80-col row) ----
__device__ __forceinline__ void frag_mma_row(
    float (&acc)[10][4], const uint32_t* Ah, const uint32_t* Al,
    uint32_t sBh, uint32_t sBl, int rB, int ldb, int n0w, int lane)
{
    #pragma unroll
    for (int ntp = 0; ntp < 5; ntp++) {
        uint32_t off = (uint32_t)((rB*ldb + n0w + ntp*16 + ((lane>>4)<<3)) << 1);
        uint32_t rh[4], rl[4];
        ldsm4t(rh, sBh + off);
        ldsm4t(rl, sBl + off);
        uint32_t bh0[2] = {rh[0], rh[1]}, bh1[2] = {rh[2], rh[3]};
        uint32_t bl0[2] = {rl[0], rl[1]}, bl1[2] = {rl[2], rl[3]};
        mmabf(acc[2*ntp],   Ah, bh0);
        mmabf(acc[2*ntp],   Ah, bl0);
        mmabf(acc[2*ntp],   Al, bh0);
        mmabf(acc[2*ntp+1], Ah, bh1);
        mmabf(acc[2*ntp+1], Ah, bl1);
        mmabf(acc[2*ntp+1], Al, bh1);
    }
}

// ============================================================
// K7a: x_new = s^T @ e.  CTA per (bc, half): M = 80 rows of x_new.
// s-half tile [160][88] per plane (stride 88 el = 176 B, 16-aligned).
// e streamed via 2-slot ring (stride 168). 2 CTAs/SM.
// smem elems: Sc_h@0 (14080), Sc_l@14080, ring@28160 (2 x 10752). 99328 B.
// ============================================================
#define XN_SCL   14080
#define XN_RING  28160
#define XN_PL    5376
#define XN_SLOT  10752
#define XN_SMEM  (49664*2)

__global__ void __launch_bounds__(320, 2) k_xn(float* __restrict__ xnew)
{
    extern __shared__ __nv_bfloat16 smb[];
    uint32_t sb = (uint32_t)__cvta_generic_to_shared(smb);
    int bc = blockIdx.x;
    int h  = blockIdx.y;
    int tid = threadIdx.x, lane = tid & 31, wid = tid >> 5;
    int wmi = wid % 5, wni = wid / 5;
    int g = lane >> 2, t4 = lane & 3;
    int m0w = wmi*16;
    int n0w = wni*80;

    const __nv_bfloat16* sh_g = g_sh + (size_t)bc*NL + h*80;
    const __nv_bfloat16* sl_g = g_sl + (size_t)bc*NL + h*80;
    const __nv_bfloat16* eh_g = g_eh + (size_t)bc*NL;
    const __nv_bfloat16* el_g = g_el + (size_t)bc*NL;

    // prologue: s columns half -> [160][88] planes (one group)
    #pragma unroll
    for (int i = 0; i < 10; i++) {
        int s = tid + i*320;              // 0..3199
        int pl = s >= 1600; int ss = s - pl*1600;
        int r = ss/10, c8 = (ss%10)*8;
        const __nv_bfloat16* src = (pl ? sl_g : sh_g) + r*160 + c8;
        cp16(sb + (uint32_t)((pl ? XN_SCL : 0) + r*88 + c8)*2, src);
    }
    CP_COMMIT();

    auto stage_e = [&](int ch, int slot) {
        uint32_t base = sb + (uint32_t)(XN_RING + slot*XN_SLOT)*2;
        #pragma unroll
        for (int i = 0; i < 4; i++) {
            int s = tid + i*320;
            int pl = s >= 640; int ss = s - pl*640;
            int r = ss/20, c8 = (ss%20)*8;
            const __nv_bfloat16* src = (pl ? el_g : eh_g) + (ch*32 + r)*160 + c8;
            cp16(base + (uint32_t)(pl*XN_PL + r*168 + c8)*2, src);
        }
        CP_COMMIT();
    };

    float acc[10][4];
    #pragma unroll
    for (int i = 0; i < 10; i++)
        acc[i][0] = acc[i][1] = acc[i][2] = acc[i][3] = 0.f;

    stage_e(0, 0);
    for (int ch = 0; ch < 5; ch++) {
        if (ch + 1 < 5) { stage_e(ch+1, (ch+1)&1); cp_wait<1>(); }
        else            { cp_wait<0>(); }
        __syncthreads();
        uint32_t stb  = sb + (uint32_t)(XN_RING + (ch&1)*XN_SLOT)*2;
        uint32_t stbl = stb + (uint32_t)XN_PL*2;
        #pragma unroll
        for (int kk = 0; kk < 32; kk += 16) {
            int kg = ch*32 + kk;
            uint32_t Ah[4], Al[4];
            uint32_t offA = (uint32_t)(((kg + (lane&7) + ((lane>>4)<<3))*88
                                        + m0w + (lane&8)) << 1);
            ldsm4t(Ah, sb + offA);
            ldsm4t(Al, sb + (uint32_t)(XN_SCL*2) + offA);
            int rB = kk + (lane&7) + (lane&8);
            frag_mma_row(acc, Ah, Al, stb, stbl, rB, 168, n0w, lane);
        }
        __syncthreads();
    }
    {
        float* X = xnew + (size_t)bc*NL;
        int r0 = h*80 + m0w + g;
        #pragma unroll
        for (int nt = 0; nt < 10; nt++) {
            int c0 = n0w + nt*8 + 2*t4;
            *(float2*)&X[(size_t)r0*160 + c0]     = make_float2(acc[nt][0], acc[nt][1]);
            *(float2*)&X[(size_t)(r0+8)*160 + c0] = make_float2(acc[nt][2], acc[nt][3]);
        }
    }
}

// ============================================================
// K7b: t = s @ a ; a_new = t @ s.  One CTA per bc, full 160 rows.
// a planes preloaded into the region t later occupies (a dead after phase1).
// All operands smem-resident; s/a loads chunked (5 groups) to overlap compute.
// smem elems: S_h@0, S_l@26880, T/A_h@53760, T/A_l@80640. 215040 B.
// warps 5(M:32 rows) x 2(N:80 cols); acc[2][10][4].
// ============================================================
#define AN_SL  26880
#define AN_TH  53760
#define AN_TL  80640
#define AN_SMEM (107520*2)

__global__ void __launch_bounds__(320, 1) k_an(float* __restrict__ anew)
{
    extern __shared__ __nv_bfloat16 smb[];
    uint32_t sb = (uint32_t)__cvta_generic_to_shared(smb);
    int bc = blockIdx.x;
    int tid = threadIdx.x, lane = tid & 31, wid = tid >> 5;
    int wmi = wid % 5, wni = wid / 5;
    int g = lane >> 2, t4 = lane & 3;
    int n0w = wni*80;

    const __nv_bfloat16* sh_g = g_sh + (size_t)bc*NL;
    const __nv_bfloat16* sl_g = g_sl + (size_t)bc*NL;

    // stage chunk ch: s columns [ch*32, +32) + a rows [ch*32, +32)  (one group)
    auto stage_ch = [&](int ch) {
        #pragma unroll
        for (int i = 0; i < 4; i++) {      // s cols chunk: 160 rows x 32 cols
            int s = tid + i*320;
            int pl = s >= 640; int ss = s - pl*640;
            int r = ss >> 2, c8 = (ss & 3)*8;
            const __nv_bfloat16* src = (pl ? sl_g : sh_g) + r*160 + ch*32 + c8;
            cp16(sb + (uint32_t)((pl ? AN_SL : 0) + r*168 + ch*32 + c8)*2, src);
        }
        #pragma unroll
        for (int i = 0; i < 4; i++) {      // a rows chunk: 32 rows x 160 cols
            int s = tid + i*320;
            int pl = s >= 640; int ss = s - pl*640;
            int r = ss/20, c8 = (ss%20)*8;
            const __nv_bfloat16* src = (pl ? g_al : g_ah) + (ch*32 + r)*160 + c8;
            cp16(sb + (uint32_t)((pl ? AN_TL : AN_TH) + (ch*32 + r)*168 + c8)*2, src);
        }
        CP_COMMIT();
    };

    stage_ch(0); stage_ch(1); stage_ch(2); stage_ch(3); stage_ch(4);

    float acc[2][10][4];
    #pragma unroll
    for (int mt = 0; mt < 2; mt++)
    #pragma unroll
    for (int i = 0; i < 10; i++)
        acc[mt][i][0] = acc[mt][i][1] = acc[mt][i][2] = acc[mt][i][3] = 0.f;

    // ---- phase 1: t = s @ a ----
    #pragma unroll
    for (int ch = 0; ch < 5; ch++) {
        switch (ch) {
            case 0: cp_wait<4>(); break;
            case 1: cp_wait<3>(); break;
            case 2: cp_wait<2>(); break;
            case 3: cp_wait<1>(); break;
            default: cp_wait<0>(); break;
        }
        __syncthreads();
        #pragma unroll
        for (int kk = 0; kk < 32; kk += 16) {
            int kg = ch*32 + kk;
            uint32_t Ah[2][4], Al[2][4];
            #pragma unroll
            for (int mt = 0; mt < 2; mt++) {
                uint32_t offA = (uint32_t)(((wmi*32 + mt*16 + (lane&15))*168
                                            + kg + ((lane>>4)<<3)) << 1);
                ldsm4(Ah[mt], sb + offA);
                ldsm4(Al[mt], sb + (uint32_t)(AN_SL*2) + offA);
            }
            int rB = kg + (lane&7) + (lane&8);
            #pragma unroll
            for (int ntp = 0; ntp < 5; ntp++) {
                uint32_t off = (uint32_t)((rB*168 + n0w + ntp*16 + ((lane>>4)<<3)) << 1);
                uint32_t rh[4], rl[4];
                ldsm4t(rh, sb + (uint32_t)(AN_TH*2) + off);
                ldsm4t(rl, sb + (uint32_t)(AN_TL*2) + off);
                uint32_t bh0[2] = {rh[0], rh[1]}, bh1[2] = {rh[2], rh[3]};
                uint32_t bl0[2] = {rl[0], rl[1]}, bl1[2] = {rl[2], rl[3]};
                #pragma unroll
                for (int mt = 0; mt < 2; mt++) {
                    mmabf(acc[mt][2*ntp],   Ah[mt], bh0);
                    mmabf(acc[mt][2*ntp],   Ah[mt], bl0);
                    mmabf(acc[mt][2*ntp],   Al[mt], bh0);
                    mmabf(acc[mt][2*ntp+1], Ah[mt], bh1);
                    mmabf(acc[mt][2*ntp+1], Ah[mt], bl1);
                    mmabf(acc[mt][2*ntp+1], Al[mt], bh1);
                }
            }
        }
    }
    __syncthreads();   // all reads of a done -> safe to overwrite with t

    // ---- t -> smem planes (overwrite a region) ----
    #pragma unroll
    for (int mt = 0; mt < 2; mt++) {
        int r0l = wmi*32 + mt*16 + g;
        #pragma unroll
        for (int nt = 0; nt < 10; nt++) {
            int c0 = n0w + nt*8 + 2*t4;
            uint32_t wh, wl;
            split_pair(acc[mt][nt][0], acc[mt][nt][1], wh, wl);
            *(uint32_t*)(smb + AN_TH + r0l*168 + c0) = wh;
            *(uint32_t*)(smb + AN_TL + r0l*168 + c0) = wl;
            split_pair(acc[mt][nt][2], acc[mt][nt][3], wh, wl);
            *(uint32_t*)(smb + AN_TH + (r0l+8)*168 + c0) = wh;
            *(uint32_t*)(smb + AN_TL + (r0l+8)*168 + c0) = wl;
        }
    }
    __syncthreads();

    // ---- phase 2: a_new = t @ s (all smem) ----
    #pragma unroll
    for (int mt = 0; mt < 2; mt++)
    #pragma unroll
    for (int i = 0; i < 10; i++)
        acc[mt][i][0] = acc[mt][i][1] = acc[mt][i][2] = acc[mt][i][3] = 0.f;
    #pragma unroll
    for (int k16 = 0; k16 < 10; k16++) {
        int kg = k16*16;
        uint32_t Ah[2][4], Al[2][4];
        #pragma unroll
        for (int mt = 0; mt < 2; mt++) {
            uint32_t offA = (uint32_t)(((wmi*32 + mt*16 + (lane&15))*168
                                        + kg + ((lane>>4)<<3)) << 1);
            ldsm4(Ah[mt], sb + (uint32_t)(AN_TH*2) + offA);
            ldsm4(Al[mt], sb + (uint32_t)(AN_TL*2) + offA);
        }
        int rB = kg + (lane&7) + (lane&8);
        #pragma unroll
        for (int ntp = 0; ntp < 5; ntp++) {
            uint32_t off = (uint32_t)((rB*168 + n0w + ntp*16 + ((lane>>4)<<3)) << 1);
            uint32_t rh[4], rl[4];
            ldsm4t(rh, sb + off);
            ldsm4t(rl, sb + (uint32_t)(AN_SL*2) + off);
            uint32_t bh0[2] = {rh[0], rh[1]}, bh1[2] = {rh[2], rh[3]};
            uint32_t bl0[2] = {rl[0], rl[1]}, bl1[2] = {rl[2], rl[3]};
            #pragma unroll
            for (int mt = 0; mt < 2; mt++) {
                mmabf(acc[mt][2*ntp],   Ah[mt], bh0);
                mmabf(acc[mt][2*ntp],   Ah[mt], bl0);
                mmabf(acc[mt][2*ntp],   Al[mt], bh0);
                mmabf(acc[mt][2*ntp+1], Ah[mt], bh1);
                mmabf(acc[mt][2*ntp+1], Ah[mt], bl1);
                mmabf(acc[mt][2*ntp+1], Al[mt], bh1);
            }
        }
    }
    {
        float* Aout = anew + (size_t)bc*NL;
        #pragma unroll
        for (int mt = 0; mt < 2; mt++) {
            int r0 = wmi*32 + mt*16 + g;
            #pragma unroll
            for (int nt = 0; nt < 10; nt++) {
                int c0 = n0w + nt*8 + 2*t4;
                *(float2*)&Aout[(size_t)r0*160 + c0] =
                    make_float2(acc[mt][nt][0], acc[mt][nt][1]);
                *(float2*)&Aout[(size_t)(r0+8)*160 + c0] =
                    make_float2(acc[mt][nt][2], acc[mt][nt][3]);
            }
        }
    }
}

// ============================================================
extern "C" void kernel_launch(void* const* d_in, const int* in_sizes, int n_in,
                              void* d_out, int out_size) {
    const float* x  = (const float*)d_in[0];
    const float* a  = (const float*)d_in[1];
    const float* We = (const float*)d_in[2];
    const float* be = (const float*)d_in[3];
    const float* Wp = (const float*)d_in[4];
    const float* bp = (const float*)d_in[5];
    float* out  = (float*)d_out;
    float* xnew = out;
    float* anew = out + (size_t)BC*NL;

    void *pMsh, *pMsl, *pxh, *pxl, *pyh, *pyl;
    cudaGetSymbolAddress(&pMsh, g_Msh); cudaGetSymbolAddress(&pMsl, g_Msl);
    cudaGetSymbolAddress(&pxh,  g_xh);  cudaGetSymbolAddress(&pxl,  g_xl);
    cudaGetSymbolAddress(&pyh,  g_yh);  cudaGetSymbolAddress(&pyl,  g_yl);

    cudaFuncSetAttribute((const void*)k_bgemm_bf,
        cudaFuncAttributeMaxDynamicSharedMemorySize, TGB::SMEM);
    cudaFuncSetAttribute((const void*)k_mix_bf,
        cudaFuncAttributeMaxDynamicSharedMemorySize, MIXB_SMEM);
    cudaFuncSetAttribute((const void*)k_softmax3,
        cudaFuncAttributeMaxDynamicSharedMemorySize, SMAX_SMEM);
    cudaFuncSetAttribute((const void*)k_xn,
        cudaFuncAttributeMaxDynamicSharedMemorySize, XN_SMEM);
    cudaFuncSetAttribute((const void*)k_an,
        cudaFuncAttributeMaxDynamicSharedMemorySize, AN_SMEM);

    k_norm_adj<<<Ndim, Ndim>>>(a);
    k_prep<<<dim3(5, 5), 64>>>();
    k_wcprep<<<(64*96 + 255)/256, 256>>>(We, Wp);
    k_xsplit<<<(int)(((size_t)BC*NL)/1024), 256>>>(x);

    // ystack = Ms @ x : A shared (sA=0), B = x planes, C = y planes (split)
    k_bgemm_bf<<<dim3(BC, 2, 2), 320, TGB::SMEM>>>(
        (const __nv_bfloat16*)pMsh, (const __nv_bfloat16*)pMsl, 0, Ndim,
        (const __nv_bfloat16*)pxh,  (const __nv_bfloat16*)pxl,  NL, Ndim,
        (__nv_bfloat16*)pyh, (__nv_bfloat16*)pyl, 2*NL, Ndim);

    // channel mix -> embed (split planes), pool (fp32)
    k_mix_bf<<<dim3(NL/160, Bdim), 320, MIXB_SMEM>>>(be, bp);

    k_softmax3<<<BC, Ndim, SMAX_SMEM>>>();

    // x_new = s^T @ e  (2 CTAs/SM)
    k_xn<<<dim3(BC, 2), 320, XN_SMEM>>>(xnew);

    // t = s @ a ; a_new = t @ s  (smem-resident)
    k_an<<<BC, 320, AN_SMEM>>>(anew);
}

// round 14
// speedup vs baseline: 1.0743x; 1.0110x over previous
#include <cuda_runtime.h>
#include <cuda_bf16.h>
#include <cstdint>

#define Bdim 32
#define Ndim 160
#define NL 25600           // 160*160
#define BC 1024            // 32*32
#define ALPHA 0.05f
#define OMA 0.95f

// ---- scratch (__device__ globals). GEMM operands stored as TWO bf16 planes
// (hi = bf16(v), lo = bf16(v - hi)); byte-neutral vs fp32. ----
__device__ __align__(16) float g_A1[Ndim*Ndim];
__device__ __align__(16) float g_A2[Ndim*Ndim];
__device__ __align__(16) __nv_bfloat16 g_Msh[2*Ndim*Ndim], g_Msl[2*Ndim*Ndim];
__device__ __align__(16) __nv_bfloat16 g_ah [Ndim*Ndim],   g_al [Ndim*Ndim];
__device__ __align__(16) __nv_bfloat16 g_Wch[64*96],       g_Wcl[64*96];
__device__ __align__(16) __nv_bfloat16 g_xh[(size_t)BC*NL],   g_xl[(size_t)BC*NL];
__device__ __align__(16) __nv_bfloat16 g_yh[(size_t)BC*2*NL], g_yl[(size_t)BC*2*NL];
__device__ __align__(16) __nv_bfloat16 g_eh[(size_t)BC*NL],   g_el[(size_t)BC*NL];
__device__ __align__(16) float g_pool[(size_t)BC*NL];
__device__ __align__(16) __nv_bfloat16 g_sh[(size_t)BC*NL],   g_sl[(size_t)BC*NL];

// ---------- helpers ----------
__device__ __forceinline__ uint32_t packbf(float v0, float v1) {
    uint32_t w; asm("cvt.rn.bf16x2.f32 %0, %1, %2;" : "=r"(w) : "f"(v1), "f"(v0));
    return w;
}
__device__ __forceinline__ void split_pair(float v0, float v1, uint32_t& wh, uint32_t& wl) {
    wh = packbf(v0, v1);
    float u0 = __uint_as_float(wh << 16);
    float u1 = __uint_as_float(wh & 0xFFFF0000u);
    wl = packbf(v0 - u0, v1 - u1);
}
__device__ __forceinline__ void splitb(float v, __nv_bfloat16* h, __nv_bfloat16* l) {
    __nv_bfloat16 hh = __float2bfloat16(v);
    *h = hh;
    *l = __float2bfloat16(v - __bfloat162float(hh));
}
__device__ __forceinline__ void mmabf(float* c, const uint32_t* a, const uint32_t* b) {
    asm volatile(
        "mma.sync.aligned.m16n8k16.row.col.f32.bf16.bf16.f32 "
        "{%0,%1,%2,%3}, {%4,%5,%6,%7}, {%8,%9}, {%0,%1,%2,%3};"
        : "+f"(c[0]), "+f"(c[1]), "+f"(c[2]), "+f"(c[3])
        : "r"(a[0]), "r"(a[1]), "r"(a[2]), "r"(a[3]), "r"(b[0]), "r"(b[1]));
}
__device__ __forceinline__ void ldsm4(uint32_t* r, uint32_t a) {
    asm volatile("ldmatrix.sync.aligned.m8n8.x4.shared.b16 {%0,%1,%2,%3}, [%4];"
        : "=r"(r[0]), "=r"(r[1]), "=r"(r[2]), "=r"(r[3]) : "r"(a));
}
__device__ __forceinline__ void ldsm4t(uint32_t* r, uint32_t a) {
    asm volatile("ldmatrix.sync.aligned.m8n8.x4.trans.shared.b16 {%0,%1,%2,%3}, [%4];"
        : "=r"(r[0]), "=r"(r[1]), "=r"(r[2]), "=r"(r[3]) : "r"(a));
}
__device__ __forceinline__ void ldsm2t(uint32_t* r, uint32_t a) {
    asm volatile("ldmatrix.sync.aligned.m8n8.x2.trans.shared.b16 {%0,%1}, [%2];"
        : "=r"(r[0]), "=r"(r[1]) : "r"(a));
}
__device__ __forceinline__ void cp16(uint32_t saddr, const void* gptr) {
    asm volatile("cp.async.cg.shared.global [%0], [%1], 16;" :: "r"(saddr), "l"(gptr));
}
#define CP_COMMIT() asm volatile("cp.async.commit_group;")
template<int N> __device__ __forceinline__ void cp_wait() {
    asm volatile("cp.async.wait_group %0;" :: "n"(N));
}

// ============================================================
// K1: row-normalized (a+I), (a^T+I) fp32; split copy of raw a
// ============================================================
__global__ void k_norm_adj(const float* __restrict__ a) {
    int v = blockIdx.x;
    int t = threadIdx.x;
    __shared__ float s1[Ndim], s2[Ndim];
    __shared__ float r1, r2;
    float av = a[v*Ndim + t];
    float aw = a[t*Ndim + v];
    s1[t] = av; s2[t] = aw;
    __syncthreads();
    if (t == 0) {
        float x1 = 0.f, x2 = 0.f;
        for (int i = 0; i < Ndim; i++) { x1 += s1[i]; x2 += s2[i]; }
        r1 = x1 + 1.f; r2 = x2 + 1.f;
    }
    __syncthreads();
    float diag = (t == v) ? 1.f : 0.f;
    g_A1[v*Ndim + t] = (av + diag) / r1;
    g_A2[v*Ndim + t] = (aw + diag) / r2;
    splitb(av, &g_ah[v*Ndim + t], &g_al[v*Ndim + t]);
}

// ============================================================
// K2: Mstack fp32 GEMM, split outputs into Ms planes
// ============================================================
__global__ void k_prep() {
    __shared__ float As1[32][36], As2[32][36], Bs1[32][36], Bs2[32][36];
    int tid = threadIdx.x;
    int tx = tid & 7, ty = tid >> 3;
    int bi = blockIdx.y, bj = blockIdx.x;
    float c1[4][4] = {}, c2[4][4] = {};
    for (int kt = 0; kt < 5; kt++) {
        #pragma unroll
        for (int it = 0; it < 4; it++) {
            int g = tid + it*64;
            int m = g >> 3, k4 = g & 7;
            float4 v1 = *(const float4*)&g_A1[(bi*32+m)*Ndim + kt*32 + k4*4];
            float4 v2 = *(const float4*)&g_A2[(bi*32+m)*Ndim + kt*32 + k4*4];
            As1[k4*4+0][m] = v1.x; As1[k4*4+1][m] = v1.y;
            As1[k4*4+2][m] = v1.z; As1[k4*4+3][m] = v1.w;
            As2[k4*4+0][m] = v2.x; As2[k4*4+1][m] = v2.y;
            As2[k4*4+2][m] = v2.z; As2[k4*4+3][m] = v2.w;
            int r = g >> 3, c4 = g & 7;
            *(float4*)&Bs1[r][c4*4] = *(const float4*)&g_A1[(kt*32+r)*Ndim + bj*32 + c4*4];
            *(float4*)&Bs2[r][c4*4] = *(const float4*)&g_A2[(kt*32+r)*Ndim + bj*32 + c4*4];
        }
        __syncthreads();
        #pragma unroll
        for (int k = 0; k < 32; k++) {
            float4 a1 = *(const float4*)&As1[k][ty*4];
            float4 a2 = *(const float4*)&As2[k][ty*4];
            float4 b1 = *(const float4*)&Bs1[k][tx*4];
            float4 b2 = *(const float4*)&Bs2[k][tx*4];
            float aa1[4] = {a1.x,a1.y,a1.z,a1.w}, aa2[4] = {a2.x,a2.y,a2.z,a2.w};
            float bb1[4] = {b1.x,b1.y,b1.z,b1.w}, bb2[4] = {b2.x,b2.y,b2.z,b2.w};
            #pragma unroll
            for (int i = 0; i < 4; i++)
            #pragma unroll
            for (int j = 0; j < 4; j++) {
                c1[i][j] += aa1[i]*bb1[j];
                c2[i][j] += aa2[i]*bb2[j];
            }
        }
        __syncthreads();
    }
    #pragma unroll
    for (int i = 0; i < 4; i++) {
        int row = bi*32 + ty*4 + i;
        int col = bj*32 + tx*4;
        float4 a1 = *(const float4*)&g_A1[row*Ndim + col];
        float4 a2 = *(const float4*)&g_A2[row*Ndim + col];
        float sv[4] = {a1.x+a2.x, a1.y+a2.y, a1.z+a2.z, a1.w+a2.w};
        #pragma unroll
        for (int j = 0; j < 4; j++) {
            splitb(OMA*sv[j], &g_Msh[row*Ndim + col + j], &g_Msl[row*Ndim + col + j]);
            splitb(ALPHA*OMA*sv[j] + OMA*OMA*(c1[i][j]+c2[i][j]),
                   &g_Msh[(160+row)*Ndim + col + j], &g_Msl[(160+row)*Ndim + col + j]);
        }
    }
}

// ============================================================
// K3: split x into planes + folded weights (merged; wc in first 24 blocks)
// ============================================================
__global__ void k_xsplit(const float* __restrict__ x,
                         const float* __restrict__ We, const float* __restrict__ Wp) {
    if (blockIdx.x < 24) {
        int idx = blockIdx.x*256 + threadIdx.x;   // < 6144 = 64*96
        int o = idx / 96, k = idx % 96;
        const float* W = (o < 32) ? We : Wp;
        int oo = o & 31;
        float v;
        if (k < 32) v = 2.f*W[oo*96 + k] + 2.f*ALPHA*(W[oo*96 + k + 32] + W[oo*96 + k + 64]);
        else        v = W[oo*96 + k];
        splitb(v, &g_Wch[idx], &g_Wcl[idx]);
    }
    size_t i4 = ((size_t)blockIdx.x*256 + threadIdx.x)*4;
    float4 v = *(const float4*)&x[i4];
    uint32_t h01, l01, h23, l23;
    split_pair(v.x, v.y, h01, l01);
    split_pair(v.z, v.w, h23, l23);
    *(uint2*)&g_xh[i4] = make_uint2(h01, h23);
    *(uint2*)&g_xl[i4] = make_uint2(l01, l23);
}

// ============================================================
// K4: batched bf16-planar GEMM (y-stage).
// Grid reordered: blockIdx.x = (m<<1)|n tile id (4 combos, fastest dim),
// blockIdx.y = bc -> the 4 CTAs of one bc are co-resident => x slice L2-hit.
// ============================================================
struct TGB {
    static const int AS = 160*40;
    static const int BS = 32*88;
    static const int STGE = 2*AS + 2*BS;
    static const int SMEM = STGE*2*2;
};

__global__ void __launch_bounds__(320, 2) k_bgemm_bf(
    const __nv_bfloat16* __restrict__ Ah, const __nv_bfloat16* __restrict__ Al,
    long sA, int lda,
    const __nv_bfloat16* __restrict__ Bh, const __nv_bfloat16* __restrict__ Bl,
    long sB, int ldb,
    __nv_bfloat16* __restrict__ Coh, __nv_bfloat16* __restrict__ Col,
    long sC, int ldc)
{
    extern __shared__ __nv_bfloat16 smb[];
    const int AS = TGB::AS, STGE = TGB::STGE;
    uint32_t sb = (uint32_t)__cvta_generic_to_shared(smb);

    int nm = blockIdx.x;
    int bc = blockIdx.y;
    int n0 = (nm & 1) * 80;
    int m0 = (nm >> 1) * 160;
    const __nv_bfloat16* Ahb = Ah + (size_t)bc*sA;
    const __nv_bfloat16* Alb = Al + (size_t)bc*sA;
    const __nv_bfloat16* Bhb = Bh + (size_t)bc*sB;
    const __nv_bfloat16* Blb = Bl + (size_t)bc*sB;

    int tid = threadIdx.x, lane = tid & 31, wid = tid >> 5;
    int wmi = wid % 5, wni = wid / 5;
    int m0w = wmi*32, n0w = wni*40;
    int g = lane >> 2, t = lane & 3;

    float acc[2][5][4] = {};

    auto stage = [&](int kt, int st) {
        uint32_t base = sb + (uint32_t)(st*STGE)*2;
        #pragma unroll
        for (int i = 0; i < 4; i++) {
            int s = tid + i*320;
            int pl = s >= 640; int ss = s - pl*640;
            int m = ss >> 2, kc = (ss & 3)*8;
            const __nv_bfloat16* src = (pl ? Alb : Ahb) + (size_t)(m0+m)*lda + kt + kc;
            cp16(base + (uint32_t)(pl*AS + m*40 + kc)*2, src);
        }
        #pragma unroll
        for (int i = 0; i < 2; i++) {
            int s = tid + i*320;
            int pl = s >= 320; int ss = s - pl*320;
            int k = ss/10, nc = (ss%10)*8;
            const __nv_bfloat16* src = (pl ? Blb : Bhb) + (size_t)(kt+k)*ldb + n0 + nc;
            cp16(base + (uint32_t)(2*AS + pl*TGB::BS + k*88 + nc)*2, src);
        }
        CP_COMMIT();
    };

    stage(0, 0);
    #pragma unroll
    for (int it = 0; it < 5; it++) {
        if (it + 1 < 5) { stage((it+1)*32, (it+1)&1); cp_wait<1>(); }
        else            { cp_wait<0>(); }
        __syncthreads();
        uint32_t sAh = sb + (uint32_t)((it&1)*STGE)*2;
        uint32_t sAl = sAh + (uint32_t)AS*2;
        uint32_t sBh = sAh + (uint32_t)(2*AS)*2;
        uint32_t sBl = sBh + (uint32_t)TGB::BS*2;
        #pragma unroll
        for (int kk = 0; kk < 32; kk += 16) {
            uint32_t Afh[2][4], Afl[2][4];
            #pragma unroll
            for (int mt = 0; mt < 2; mt++) {
                uint32_t off = (uint32_t)(((m0w + mt*16 + (lane&15))*40
                                           + kk + ((lane>>4)<<3)) << 1);
                ldsm4(Afh[mt], sAh + off);
                ldsm4(Afl[mt], sAl + off);
            }
            uint32_t Bfh[5][2], Bfl[5][2];
            int rB = kk + (lane&7) + (lane&8);
            #pragma unroll
            for (int ntp = 0; ntp < 2; ntp++) {
                uint32_t off = (uint32_t)((rB*88 + n0w + ntp*16 + ((lane>>4)<<3)) << 1);
                uint32_t rh[4], rl[4];
                ldsm4t(rh, sBh + off);
                ldsm4t(rl, sBl + off);
                Bfh[2*ntp][0]=rh[0]; Bfh[2*ntp][1]=rh[1]; Bfh[2*ntp+1][0]=rh[2]; Bfh[2*ntp+1][1]=rh[3];
                Bfl[2*ntp][0]=rl[0]; Bfl[2*ntp][1]=rl[1]; Bfl[2*ntp+1][0]=rl[2]; Bfl[2*ntp+1][1]=rl[3];
            }
            {
                uint32_t off = (uint32_t)((rB*88 + n0w + 32) << 1);
                ldsm2t(Bfh[4], sBh + off);
                ldsm2t(Bfl[4], sBl + off);
            }
            #pragma unroll
            for (int nt = 0; nt < 5; nt++)
            #pragma unroll
            for (int mt = 0; mt < 2; mt++) {
                mmabf(acc[mt][nt], Afh[mt], Bfh[nt]);
                mmabf(acc[mt][nt], Afh[mt], Bfl[nt]);
                mmabf(acc[mt][nt], Afl[mt], Bfh[nt]);
            }
        }
        __syncthreads();
    }
    #pragma unroll
    for (int mt = 0; mt < 2; mt++) {
        int r0 = m0 + m0w + mt*16 + g;
        #pragma unroll
        for (int nt = 0; nt < 5; nt++) {
            int c0 = n0 + n0w + nt*8 + 2*t;
            __nv_bfloat16* Ch = Coh + (size_t)bc*sC;
            __nv_bfloat16* Cl = Col + (size_t)bc*sC;
            uint32_t wh, wl;
            split_pair(acc[mt][nt][0], acc[mt][nt][1], wh, wl);
            *(uint32_t*)&Ch[(size_t)r0*ldc + c0] = wh;
            *(uint32_t*)&Cl[(size_t)r0*ldc + c0] = wl;
            split_pair(acc[mt][nt][2], acc[mt][nt][3], wh, wl);
            *(uint32_t*)&Ch[(size_t)(r0+8)*ldc + c0] = wh;
            *(uint32_t*)&Cl[(size_t)(r0+8)*ldc + c0] = wl;
        }
    }
}

// ============================================================
// K5: channel mix, bf16 planar (unchanged).
// ============================================================
#define MIXB_AS (64*40)
#define MIXB_BS (32*168)
#define MIXB_STGE (2*MIXB_AS + 2*MIXB_BS)
#define MIXB_SMEM (MIXB_STGE*2*2)

__global__ void __launch_bounds__(320, 2) k_mix_bf(
    const float* __restrict__ be, const float* __restrict__ bp)
{
    extern __shared__ __nv_bfloat16 smb[];
    uint32_t sb = (uint32_t)__cvta_generic_to_shared(smb);
    int b  = blockIdx.y;
    int p0 = blockIdx.x * 160;
    int tid = threadIdx.x, lane = tid & 31, wid = tid >> 5;
    int wmi = wid & 1, wni = wid >> 1;
    int m0w = wmi*32, n0w = wni*32;
    int g = lane >> 2, t = lane & 3;

    float acc[2][4][4] = {};

    auto stage = [&](int ktc, int st) {
        uint32_t base = sb + (uint32_t)(st*MIXB_STGE)*2;
        #pragma unroll
        for (int i = 0; i < 2; i++) {
            int s = tid + i*320;
            if (s < 512) {
                int pl = s >= 256; int ss = s & 255;
                int m = ss >> 2, kc = (ss & 3)*8;
                const __nv_bfloat16* src = (pl ? g_Wcl : g_Wch) + m*96 + ktc + kc;
                cp16(base + (uint32_t)(pl*MIXB_AS + m*40 + kc)*2, src);
            }
        }
        #pragma unroll
        for (int i = 0; i < 4; i++) {
            int s = tid + i*320;
            int pl = s >= 640; int ss = s - pl*640;
            int k = ss/20, mc = (ss%20)*8;
            int kg = ktc + k;
            int c = kg & 31;
            const __nv_bfloat16* src;
            if (pl) {
                if (kg < 32)      src = g_xl + ((size_t)b*32 + c)*NL;
                else if (kg < 64) src = g_yl + ((size_t)b*32 + c)*(2*NL);
                else              src = g_yl + ((size_t)b*32 + c)*(2*NL) + NL;
            } else {
                if (kg < 32)      src = g_xh + ((size_t)b*32 + c)*NL;
                else if (kg < 64) src = g_yh + ((size_t)b*32 + c)*(2*NL);
                else              src = g_yh + ((size_t)b*32 + c)*(2*NL) + NL;
            }
            cp16(base + (uint32_t)(2*MIXB_AS + pl*MIXB_BS + k*168 + mc)*2, src + p0 + mc);
        }
        CP_COMMIT();
    };

    stage(0, 0);
    #pragma unroll
    for (int it = 0; it < 3; it++) {
        if (it + 1 < 3) { stage((it+1)*32, (it+1)&1); cp_wait<1>(); }
        else            { cp_wait<0>(); }
        __syncthreads();
        uint32_t sAh = sb + (uint32_t)((it&1)*MIXB_STGE)*2;
        uint32_t sAl = sAh + (uint32_t)MIXB_AS*2;
        uint32_t sBh = sAh + (uint32_t)(2*MIXB_AS)*2;
        uint32_t sBl = sBh + (uint32_t)MIXB_BS*2;
        #pragma unroll
        for (int kk = 0; kk < 32; kk += 16) {
            uint32_t Afh[2][4], Afl[2][4];
            #pragma unroll
            for (int mt = 0; mt < 2; mt++) {
                uint32_t off = (uint32_t)(((m0w + mt*16 + (lane&15))*40
                                           + kk + ((lane>>4)<<3)) << 1);
                ldsm4(Afh[mt], sAh + off);
                ldsm4(Afl[mt], sAl + off);
            }
            uint32_t Bfh[4][2], Bfl[4][2];
            int rB = kk + (lane&7) + (lane&8);
            #pragma unroll
            for (int ntp = 0; ntp < 2; ntp++) {
                uint32_t off = (uint32_t)((rB*168 + n0w + ntp*16 + ((lane>>4)<<3)) << 1);
                uint32_t rh[4], rl[4];
                ldsm4t(rh, sBh + off);
                ldsm4t(rl, sBl + off);
                Bfh[2*ntp][0]=rh[0]; Bfh[2*ntp][1]=rh[1]; Bfh[2*ntp+1][0]=rh[2]; Bfh[2*ntp+1][1]=rh[3];
                Bfl[2*ntp][0]=rl[0]; Bfl[2*ntp][1]=rl[1]; Bfl[2*ntp+1][0]=rl[2]; Bfl[2*ntp+1][1]=rl[3];
            }
            #pragma unroll
            for (int nt = 0; nt < 4; nt++)
            #pragma unroll
            for (int mt = 0; mt < 2; mt++) {
                mmabf(acc[mt][nt], Afh[mt], Bfh[nt]);
                mmabf(acc[mt][nt], Afh[mt], Bfl[nt]);
                mmabf(acc[mt][nt], Afl[mt], Bfh[nt]);
            }
        }
        __syncthreads();
    }
    #pragma unroll
    for (int mt = 0; mt < 2; mt++) {
        #pragma unroll
        for (int rr = 0; rr < 2; rr++) {
            int o = m0w + mt*16 + g + rr*8;
            float bias = 2.f * ((o < 32) ? be[o] : bp[o-32]);
            int oo = o & 31;
            size_t base = ((size_t)b*32 + oo)*NL + p0;
            #pragma unroll
            for (int nt = 0; nt < 4; nt++) {
                int c0 = n0w + nt*8 + 2*t;
                float u0 = acc[mt][nt][rr*2+0] + bias;
                float u1 = acc[mt][nt][rr*2+1] + bias;
                if (o < 32) {
                    uint32_t wh, wl;
                    split_pair(u0, u1, wh, wl);
                    *(uint32_t*)&g_eh[base + c0] = wh;
                    *(uint32_t*)&g_el[base + c0] = wl;
                } else {
                    *(float2*)&g_pool[base + c0] = make_float2(u0, u1);
                }
            }
        }
    }
}

// ============================================================
// K6: softmax over node axis; split bf16 planar output
// ============================================================
#define SMAX_SMEM (160*161*4)
__global__ void k_softmax3() {
    extern __shared__ float sp[];
    int bc = blockIdx.x;
    int l = threadIdx.x;
    const float* p = g_pool + (size_t)bc*NL;
    for (int n = 0; n < Ndim; n++)
        sp[n*161 + l] = p[n*Ndim + l];
    __syncthreads();
    float m = -3.4e38f, d = 0.f;
    #pragma unroll 4
    for (int n = 0; n < Ndim; n++) {
        float v = sp[n*161 + l];
        float m2 = fmaxf(m, v);
        d = d * __expf(m - m2) + __expf(v - m2);
        m = m2;
    }
    float inv = 1.f / d;
    __nv_bfloat16* sh = g_sh + (size_t)bc*NL;
    __nv_bfloat16* sl = g_sl + (size_t)bc*NL;
    #pragma unroll 4
    for (int n = 0; n < Ndim; n++) {
        float v = __expf(sp[n*161 + l] - m) * inv;
        splitb(v, &sh[n*Ndim + l], &sl[n*Ndim + l]);
    }
}

// ---- shared B-fragment mma helper (80-col row) ----
__device__ __forceinline__ void frag_mma_row(
    float (&acc)[10][4], const uint32_t* Ah, const uint32_t* Al,
    uint32_t sBh, uint32_t sBl, int rB, int ldb, int n0w, int lane)
{
    #pragma unroll
    for (int ntp = 0; ntp < 5; ntp++) {
        uint32_t off = (uint32_t)((rB*ldb + n0w + ntp*16 + ((lane>>4)<<3)) << 1);
        uint32_t rh[4], rl[4];
        ldsm4t(rh, sBh + off);
        ldsm4t(rl, sBl + off);
        uint32_t bh0[2] = {rh[0], rh[1]}, bh1[2] = {rh[2], rh[3]};
        uint32_t bl0[2] = {rl[0], rl[1]}, bl1[2] = {rl[2], rl[3]};
        mmabf(acc[2*ntp],   Ah, bh0);
        mmabf(acc[2*ntp],   Ah, bl0);
        mmabf(acc[2*ntp],   Al, bh0);
        mmabf(acc[2*ntp+1], Ah, bh1);
        mmabf(acc[2*ntp+1], Ah, bl1);
        mmabf(acc[2*ntp+1], Al, bh1);
    }
}

// ============================================================
// K7a: x_new = s^T @ e.  Grid (2, BC): h fastest -> both halves of a bc
// co-resident -> e L2-hit. s-half tile [160][88]/plane. 2 CTAs/SM.
// ============================================================
#define XN_SCL   14080
#define XN_RING  28160
#define XN_PL    5376
#define XN_SLOT  10752
#define XN_SMEM  (49664*2)

__global__ void __launch_bounds__(320, 2) k_xn(float* __restrict__ xnew)
{
    extern __shared__ __nv_bfloat16 smb[];
    uint32_t sb = (uint32_t)__cvta_generic_to_shared(smb);
    int h  = blockIdx.x;
    int bc = blockIdx.y;
    int tid = threadIdx.x, lane = tid & 31, wid = tid >> 5;
    int wmi = wid % 5, wni = wid / 5;
    int g = lane >> 2, t4 = lane & 3;
    int m0w = wmi*16;
    int n0w = wni*80;

    const __nv_bfloat16* sh_g = g_sh + (size_t)bc*NL + h*80;
    const __nv_bfloat16* sl_g = g_sl + (size_t)bc*NL + h*80;
    const __nv_bfloat16* eh_g = g_eh + (size_t)bc*NL;
    const __nv_bfloat16* el_g = g_el + (size_t)bc*NL;

    // prologue: s columns half -> [160][88] planes (one group)
    #pragma unroll
    for (int i = 0; i < 10; i++) {
        int s = tid + i*320;
        int pl = s >= 1600; int ss = s - pl*1600;
        int r = ss/10, c8 = (ss%10)*8;
        const __nv_bfloat16* src = (pl ? sl_g : sh_g) + r*160 + c8;
        cp16(sb + (uint32_t)((pl ? XN_SCL : 0) + r*88 + c8)*2, src);
    }
    CP_COMMIT();

    auto stage_e = [&](int ch, int slot) {
        uint32_t base = sb + (uint32_t)(XN_RING + slot*XN_SLOT)*2;
        #pragma unroll
        for (int i = 0; i < 4; i++) {
            int s = tid + i*320;
            int pl = s >= 640; int ss = s - pl*640;
            int r = ss/20, c8 = (ss%20)*8;
            const __nv_bfloat16* src = (pl ? el_g : eh_g) + (ch*32 + r)*160 + c8;
            cp16(base + (uint32_t)(pl*XN_PL + r*168 + c8)*2, src);
        }
        CP_COMMIT();
    };

    float acc[10][4];
    #pragma unroll
    for (int i = 0; i < 10; i++)
        acc[i][0] = acc[i][1] = acc[i][2] = acc[i][3] = 0.f;

    stage_e(0, 0);
    for (int ch = 0; ch < 5; ch++) {
        if (ch + 1 < 5) { stage_e(ch+1, (ch+1)&1); cp_wait<1>(); }
        else            { cp_wait<0>(); }
        __syncthreads();
        uint32_t stb  = sb + (uint32_t)(XN_RING + (ch&1)*XN_SLOT)*2;
        uint32_t stbl = stb + (uint32_t)XN_PL*2;
        #pragma unroll
        for (int kk = 0; kk < 32; kk += 16) {
            int kg = ch*32 + kk;
            uint32_t Ah[4], Al[4];
            uint32_t offA = (uint32_t)(((kg + (lane&7) + ((lane>>4)<<3))*88
                                        + m0w + (lane&8)) << 1);
            ldsm4t(Ah, sb + offA);
            ldsm4t(Al, sb + (uint32_t)(XN_SCL*2) + offA);
            int rB = kk + (lane&7) + (lane&8);
            frag_mma_row(acc, Ah, Al, stb, stbl, rB, 168, n0w, lane);
        }
        __syncthreads();
    }
    {
        float* X = xnew + (size_t)bc*NL;
        int r0 = h*80 + m0w + g;
        #pragma unroll
        for (int nt = 0; nt < 10; nt++) {
            int c0 = n0w + nt*8 + 2*t4;
            *(float2*)&X[(size_t)r0*160 + c0]     = make_float2(acc[nt][0], acc[nt][1]);
            *(float2*)&X[(size_t)(r0+8)*160 + c0] = make_float2(acc[nt][2], acc[nt][3]);
        }
    }
}

// ============================================================
// K7b: t = s @ a ; a_new = t @ s.  One CTA per bc, full 160 rows.
// a planes preloaded into the region t later occupies. All smem-resident.
// ============================================================
#define AN_SL  26880
#define AN_TH  53760
#define AN_TL  80640
#define AN_SMEM (107520*2)

__global__ void __launch_bounds__(320, 1) k_an(float* __restrict__ anew)
{
    extern __shared__ __nv_bfloat16 smb[];
    uint32_t sb = (uint32_t)__cvta_generic_to_shared(smb);
    int bc = blockIdx.x;
    int tid = threadIdx.x, lane = tid & 31, wid = tid >> 5;
    int wmi = wid % 5, wni = wid / 5;
    int g = lane >> 2, t4 = lane & 3;
    int n0w = wni*80;

    const __nv_bfloat16* sh_g = g_sh + (size_t)bc*NL;
    const __nv_bfloat16* sl_g = g_sl + (size_t)bc*NL;

    auto stage_ch = [&](int ch) {
        #pragma unroll
        for (int i = 0; i < 4; i++) {      // s cols chunk: 160 rows x 32 cols
            int s = tid + i*320;
            int pl = s >= 640; int ss = s - pl*640;
            int r = ss >> 2, c8 = (ss & 3)*8;
            const __nv_bfloat16* src = (pl ? sl_g : sh_g) + r*160 + ch*32 + c8;
            cp16(sb + (uint32_t)((pl ? AN_SL : 0) + r*168 + ch*32 + c8)*2, src);
        }
        #pragma unroll
        for (int i = 0; i < 4; i++) {      // a rows chunk: 32 rows x 160 cols
            int s = tid + i*320;
            int pl = s >= 640; int ss = s - pl*640;
            int r = ss/20, c8 = (ss%20)*8;
            const __nv_bfloat16* src = (pl ? g_al : g_ah) + (ch*32 + r)*160 + c8;
            cp16(sb + (uint32_t)((pl ? AN_TL : AN_TH) + (ch*32 + r)*168 + c8)*2, src);
        }
        CP_COMMIT();
    };

    stage_ch(0); stage_ch(1); stage_ch(2); stage_ch(3); stage_ch(4);

    float acc[2][10][4];
    #pragma unroll
    for (int mt = 0; mt < 2; mt++)
    #pragma unroll
    for (int i = 0; i < 10; i++)
        acc[mt][i][0] = acc[mt][i][1] = acc[mt][i][2] = acc[mt][i][3] = 0.f;

    // ---- phase 1: t = s @ a ----
    #pragma unroll
    for (int ch = 0; ch < 5; ch++) {
        switch (ch) {
            case 0: cp_wait<4>(); break;
            case 1: cp_wait<3>(); break;
            case 2: cp_wait<2>(); break;
            case 3: cp_wait<1>(); break;
            default: cp_wait<0>(); break;
        }
        __syncthreads();
        #pragma unroll
        for (int kk = 0; kk < 32; kk += 16) {
            int kg = ch*32 + kk;
            uint32_t Ah[2][4], Al[2][4];
            #pragma unroll
            for (int mt = 0; mt < 2; mt++) {
                uint32_t offA = (uint32_t)(((wmi*32 + mt*16 + (lane&15))*168
                                            + kg + ((lane>>4)<<3)) << 1);
                ldsm4(Ah[mt], sb + offA);
                ldsm4(Al[mt], sb + (uint32_t)(AN_SL*2) + offA);
            }
            int rB = kg + (lane&7) + (lane&8);
            #pragma unroll
            for (int ntp = 0; ntp < 5; ntp++) {
                uint32_t off = (uint32_t)((rB*168 + n0w + ntp*16 + ((lane>>4)<<3)) << 1);
                uint32_t rh[4], rl[4];
                ldsm4t(rh, sb + (uint32_t)(AN_TH*2) + off);
                ldsm4t(rl, sb + (uint32_t)(AN_TL*2) + off);
                uint32_t bh0[2] = {rh[0], rh[1]}, bh1[2] = {rh[2], rh[3]};
                uint32_t bl0[2] = {rl[0], rl[1]}, bl1[2] = {rl[2], rl[3]};
                #pragma unroll
                for (int mt = 0; mt < 2; mt++) {
                    mmabf(acc[mt][2*ntp],   Ah[mt], bh0);
                    mmabf(acc[mt][2*ntp],   Ah[mt], bl0);
                    mmabf(acc[mt][2*ntp],   Al[mt], bh0);
                    mmabf(acc[mt][2*ntp+1], Ah[mt], bh1);
                    mmabf(acc[mt][2*ntp+1], Ah[mt], bl1);
                    mmabf(acc[mt][2*ntp+1], Al[mt], bh1);
                }
            }
        }
    }
    __syncthreads();   // all reads of a done -> safe to overwrite with t

    // ---- t -> smem planes (overwrite a region) ----
    #pragma unroll
    for (int mt = 0; mt < 2; mt++) {
        int r0l = wmi*32 + mt*16 + g;
        #pragma unroll
        for (int nt = 0; nt < 10; nt++) {
            int c0 = n0w + nt*8 + 2*t4;
            uint32_t wh, wl;
            split_pair(acc[mt][nt][0], acc[mt][nt][1], wh, wl);
            *(uint32_t*)(smb + AN_TH + r0l*168 + c0) = wh;
            *(uint32_t*)(smb + AN_TL + r0l*168 + c0) = wl;
            split_pair(acc[mt][nt][2], acc[mt][nt][3], wh, wl);
            *(uint32_t*)(smb + AN_TH + (r0l+8)*168 + c0) = wh;
            *(uint32_t*)(smb + AN_TL + (r0l+8)*168 + c0) = wl;
        }
    }
    __syncthreads();

    // ---- phase 2: a_new = t @ s (all smem) ----
    #pragma unroll
    for (int mt = 0; mt < 2; mt++)
    #pragma unroll
    for (int i = 0; i < 10; i++)
        acc[mt][i][0] = acc[mt][i][1] = acc[mt][i][2] = acc[mt][i][3] = 0.f;
    #pragma unroll
    for (int k16 = 0; k16 < 10; k16++) {
        int kg = k16*16;
        uint32_t Ah[2][4], Al[2][4];
        #pragma unroll
        for (int mt = 0; mt < 2; mt++) {
            uint32_t offA = (uint32_t)(((wmi*32 + mt*16 + (lane&15))*168
                                        + kg + ((lane>>4)<<3)) << 1);
            ldsm4(Ah[mt], sb + (uint32_t)(AN_TH*2) + offA);
            ldsm4(Al[mt], sb + (uint32_t)(AN_TL*2) + offA);
        }
        int rB = kg + (lane&7) + (lane&8);
        #pragma unroll
        for (int ntp = 0; ntp < 5; ntp++) {
            uint32_t off = (uint32_t)((rB*168 + n0w + ntp*16 + ((lane>>4)<<3)) << 1);
            uint32_t rh[4], rl[4];
            ldsm4t(rh, sb + off);
            ldsm4t(rl, sb + (uint32_t)(AN_SL*2) + off);
            uint32_t bh0[2] = {rh[0], rh[1]}, bh1[2] = {rh[2], rh[3]};
            uint32_t bl0[2] = {rl[0], rl[1]}, bl1[2] = {rl[2], rl[3]};
            #pragma unroll
            for (int mt = 0; mt < 2; mt++) {
                mmabf(acc[mt][2*ntp],   Ah[mt], bh0);
                mmabf(acc[mt][2*ntp],   Ah[mt], bl0);
                mmabf(acc[mt][2*ntp],   Al[mt], bh0);
                mmabf(acc[mt][2*ntp+1], Ah[mt], bh1);
                mmabf(acc[mt][2*ntp+1], Ah[mt], bl1);
                mmabf(acc[mt][2*ntp+1], Al[mt], bh1);
            }
        }
    }
    {
        float* Aout = anew + (size_t)bc*NL;
        #pragma unroll
        for (int mt = 0; mt < 2; mt++) {
            int r0 = wmi*32 + mt*16 + g;
            #pragma unroll
            for (int nt = 0; nt < 10; nt++) {
                int c0 = n0w + nt*8 + 2*t4;
                *(float2*)&Aout[(size_t)r0*160 + c0] =
                    make_float2(acc[mt][nt][0], acc[mt][nt][1]);
                *(float2*)&Aout[(size_t)(r0+8)*160 + c0] =
                    make_float2(acc[mt][nt][2], acc[mt][nt][3]);
            }
        }
    }
}

// ============================================================
extern "C" void kernel_launch(void* const* d_in, const int* in_sizes, int n_in,
                              void* d_out, int out_size) {
    const float* x  = (const float*)d_in[0];
    const float* a  = (const float*)d_in[1];
    const float* We = (const float*)d_in[2];
    const float* be = (const float*)d_in[3];
    const float* Wp = (const float*)d_in[4];
    const float* bp = (const float*)d_in[5];
    float* out  = (float*)d_out;
    float* xnew = out;
    float* anew = out + (size_t)BC*NL;

    void *pMsh, *pMsl, *pxh, *pxl, *pyh, *pyl;
    cudaGetSymbolAddress(&pMsh, g_Msh); cudaGetSymbolAddress(&pMsl, g_Msl);
    cudaGetSymbolAddress(&pxh,  g_xh);  cudaGetSymbolAddress(&pxl,  g_xl);
    cudaGetSymbolAddress(&pyh,  g_yh);  cudaGetSymbolAddress(&pyl,  g_yl);

    cudaFuncSetAttribute((const void*)k_bgemm_bf,
        cudaFuncAttributeMaxDynamicSharedMemorySize, TGB::SMEM);
    cudaFuncSetAttribute((const void*)k_mix_bf,
        cudaFuncAttributeMaxDynamicSharedMemorySize, MIXB_SMEM);
    cudaFuncSetAttribute((const void*)k_softmax3,
        cudaFuncAttributeMaxDynamicSharedMemorySize, SMAX_SMEM);
    cudaFuncSetAttribute((const void*)k_xn,
        cudaFuncAttributeMaxDynamicSharedMemorySize, XN_SMEM);
    cudaFuncSetAttribute((const void*)k_an,
        cudaFuncAttributeMaxDynamicSharedMemorySize, AN_SMEM);

    k_norm_adj<<<Ndim, Ndim>>>(a);
    k_prep<<<dim3(5, 5), 64>>>();
    k_xsplit<<<(int)(((size_t)BC*NL)/1024), 256>>>(x, We, Wp);

    // ystack = Ms @ x : (n,m) fastest for x L2 reuse
    k_bgemm_bf<<<dim3(4, BC), 320, TGB::SMEM>>>(
        (const __nv_bfloat16*)pMsh, (const __nv_bfloat16*)pMsl, 0, Ndim,
        (const __nv_bfloat16*)pxh,  (const __nv_bfloat16*)pxl,  NL, Ndim,
        (__nv_bfloat16*)pyh, (__nv_bfloat16*)pyl, 2*NL, Ndim);

    // channel mix -> embed (split planes), pool (fp32)
    k_mix_bf<<<dim3(NL/160, Bdim), 320, MIXB_SMEM>>>(be, bp);

    k_softmax3<<<BC, Ndim, SMAX_SMEM>>>();

    // x_new = s^T @ e  (h fastest for e L2 reuse; 2 CTAs/SM)
    k_xn<<<dim3(2, BC), 320, XN_SMEM>>>(xnew);

    // t = s @ a ; a_new = t @ s  (smem-resident)
    k_an<<<BC, 320, AN_SMEM>>>(anew);
}

// round 15
// speedup vs baseline: 1.1115x; 1.0346x over previous
#include <cuda_runtime.h>
#include <cuda_bf16.h>
#include <cstdint>

#define Bdim 32
#define Ndim 160
#define NL 25600           // 160*160
#define BC 1024            // 32*32
#define ALPHA 0.05f
#define OMA 0.95f

// ---- scratch (__device__ globals). GEMM operands stored as TWO bf16 planes
// (hi = bf16(v), lo = bf16(v - hi)); byte-neutral vs fp32. ----
__device__ __align__(16) float g_A1[Ndim*Ndim];
__device__ __align__(16) float g_A2[Ndim*Ndim];
__device__ __align__(16) __nv_bfloat16 g_Msh[2*Ndim*Ndim], g_Msl[2*Ndim*Ndim];
__device__ __align__(16) __nv_bfloat16 g_ah [Ndim*Ndim],   g_al [Ndim*Ndim];
__device__ __align__(16) __nv_bfloat16 g_Wch[64*96],       g_Wcl[64*96];
__device__ __align__(16) __nv_bfloat16 g_xh[(size_t)BC*NL],   g_xl[(size_t)BC*NL];
__device__ __align__(16) __nv_bfloat16 g_yh[(size_t)BC*2*NL], g_yl[(size_t)BC*2*NL];
__device__ __align__(16) __nv_bfloat16 g_eh[(size_t)BC*NL],   g_el[(size_t)BC*NL];
__device__ __align__(16) float g_pool[(size_t)BC*NL];
__device__ __align__(16) __nv_bfloat16 g_sh[(size_t)BC*NL],   g_sl[(size_t)BC*NL];

// ---------- helpers ----------
__device__ __forceinline__ uint32_t packbf(float v0, float v1) {
    uint32_t w; asm("cvt.rn.bf16x2.f32 %0, %1, %2;" : "=r"(w) : "f"(v1), "f"(v0));
    return w;
}
__device__ __forceinline__ void split_pair(float v0, float v1, uint32_t& wh, uint32_t& wl) {
    wh = packbf(v0, v1);
    float u0 = __uint_as_float(wh << 16);
    float u1 = __uint_as_float(wh & 0xFFFF0000u);
    wl = packbf(v0 - u0, v1 - u1);
}
__device__ __forceinline__ void splitb(float v, __nv_bfloat16* h, __nv_bfloat16* l) {
    __nv_bfloat16 hh = __float2bfloat16(v);
    *h = hh;
    *l = __float2bfloat16(v - __bfloat162float(hh));
}
__device__ __forceinline__ void mmabf(float* c, const uint32_t* a, const uint32_t* b) {
    asm volatile(
        "mma.sync.aligned.m16n8k16.row.col.f32.bf16.bf16.f32 "
        "{%0,%1,%2,%3}, {%4,%5,%6,%7}, {%8,%9}, {%0,%1,%2,%3};"
        : "+f"(c[0]), "+f"(c[1]), "+f"(c[2]), "+f"(c[3])
        : "r"(a[0]), "r"(a[1]), "r"(a[2]), "r"(a[3]), "r"(b[0]), "r"(b[1]));
}
__device__ __forceinline__ void ldsm4(uint32_t* r, uint32_t a) {
    asm volatile("ldmatrix.sync.aligned.m8n8.x4.shared.b16 {%0,%1,%2,%3}, [%4];"
        : "=r"(r[0]), "=r"(r[1]), "=r"(r[2]), "=r"(r[3]) : "r"(a));
}
__device__ __forceinline__ void ldsm4t(uint32_t* r, uint32_t a) {
    asm volatile("ldmatrix.sync.aligned.m8n8.x4.trans.shared.b16 {%0,%1,%2,%3}, [%4];"
        : "=r"(r[0]), "=r"(r[1]), "=r"(r[2]), "=r"(r[3]) : "r"(a));
}
__device__ __forceinline__ void ldsm2t(uint32_t* r, uint32_t a) {
    asm volatile("ldmatrix.sync.aligned.m8n8.x2.trans.shared.b16 {%0,%1}, [%2];"
        : "=r"(r[0]), "=r"(r[1]) : "r"(a));
}
__device__ __forceinline__ void cp16(uint32_t saddr, const void* gptr) {
    asm volatile("cp.async.cg.shared.global [%0], [%1], 16;" :: "r"(saddr), "l"(gptr));
}
#define CP_COMMIT() asm volatile("cp.async.commit_group;")
template<int N> __device__ __forceinline__ void cp_wait() {
    asm volatile("cp.async.wait_group %0;" :: "n"(N));
}

// ============================================================
// K1: row-normalized (a+I), (a^T+I) fp32; split copy of raw a
// ============================================================
__global__ void k_norm_adj(const float* __restrict__ a) {
    int v = blockIdx.x;
    int t = threadIdx.x;
    __shared__ float s1[Ndim], s2[Ndim];
    __shared__ float r1, r2;
    float av = a[v*Ndim + t];
    float aw = a[t*Ndim + v];
    s1[t] = av; s2[t] = aw;
    __syncthreads();
    if (t == 0) {
        float x1 = 0.f, x2 = 0.f;
        for (int i = 0; i < Ndim; i++) { x1 += s1[i]; x2 += s2[i]; }
        r1 = x1 + 1.f; r2 = x2 + 1.f;
    }
    __syncthreads();
    float diag = (t == v) ? 1.f : 0.f;
    g_A1[v*Ndim + t] = (av + diag) / r1;
    g_A2[v*Ndim + t] = (aw + diag) / r2;
    splitb(av, &g_ah[v*Ndim + t], &g_al[v*Ndim + t]);
}

// ============================================================
// K2: Mstack fp32 GEMM, split outputs into Ms planes
// ============================================================
__global__ void k_prep() {
    __shared__ float As1[32][36], As2[32][36], Bs1[32][36], Bs2[32][36];
    int tid = threadIdx.x;
    int tx = tid & 7, ty = tid >> 3;
    int bi = blockIdx.y, bj = blockIdx.x;
    float c1[4][4] = {}, c2[4][4] = {};
    for (int kt = 0; kt < 5; kt++) {
        #pragma unroll
        for (int it = 0; it < 4; it++) {
            int g = tid + it*64;
            int m = g >> 3, k4 = g & 7;
            float4 v1 = *(const float4*)&g_A1[(bi*32+m)*Ndim + kt*32 + k4*4];
            float4 v2 = *(const float4*)&g_A2[(bi*32+m)*Ndim + kt*32 + k4*4];
            As1[k4*4+0][m] = v1.x; As1[k4*4+1][m] = v1.y;
            As1[k4*4+2][m] = v1.z; As1[k4*4+3][m] = v1.w;
            As2[k4*4+0][m] = v2.x; As2[k4*4+1][m] = v2.y;
            As2[k4*4+2][m] = v2.z; As2[k4*4+3][m] = v2.w;
            int r = g >> 3, c4 = g & 7;
            *(float4*)&Bs1[r][c4*4] = *(const float4*)&g_A1[(kt*32+r)*Ndim + bj*32 + c4*4];
            *(float4*)&Bs2[r][c4*4] = *(const float4*)&g_A2[(kt*32+r)*Ndim + bj*32 + c4*4];
        }
        __syncthreads();
        #pragma unroll
        for (int k = 0; k < 32; k++) {
            float4 a1 = *(const float4*)&As1[k][ty*4];
            float4 a2 = *(const float4*)&As2[k][ty*4];
            float4 b1 = *(const float4*)&Bs1[k][tx*4];
            float4 b2 = *(const float4*)&Bs2[k][tx*4];
            float aa1[4] = {a1.x,a1.y,a1.z,a1.w}, aa2[4] = {a2.x,a2.y,a2.z,a2.w};
            float bb1[4] = {b1.x,b1.y,b1.z,b1.w}, bb2[4] = {b2.x,b2.y,b2.z,b2.w};
            #pragma unroll
            for (int i = 0; i < 4; i++)
            #pragma unroll
            for (int j = 0; j < 4; j++) {
                c1[i][j] += aa1[i]*bb1[j];
                c2[i][j] += aa2[i]*bb2[j];
            }
        }
        __syncthreads();
    }
    #pragma unroll
    for (int i = 0; i < 4; i++) {
        int row = bi*32 + ty*4 + i;
        int col = bj*32 + tx*4;
        float4 a1 = *(const float4*)&g_A1[row*Ndim + col];
        float4 a2 = *(const float4*)&g_A2[row*Ndim + col];
        float sv[4] = {a1.x+a2.x, a1.y+a2.y, a1.z+a2.z, a1.w+a2.w};
        #pragma unroll
        for (int j = 0; j < 4; j++) {
            splitb(OMA*sv[j], &g_Msh[row*Ndim + col + j], &g_Msl[row*Ndim + col + j]);
            splitb(ALPHA*OMA*sv[j] + OMA*OMA*(c1[i][j]+c2[i][j]),
                   &g_Msh[(160+row)*Ndim + col + j], &g_Msl[(160+row)*Ndim + col + j]);
        }
    }
}

// ============================================================
// K3: split x into planes + folded weights (merged)
// ============================================================
__global__ void k_xsplit(const float* __restrict__ x,
                         const float* __restrict__ We, const float* __restrict__ Wp) {
    if (blockIdx.x < 24) {
        int idx = blockIdx.x*256 + threadIdx.x;
        int o = idx / 96, k = idx % 96;
        const float* W = (o < 32) ? We : Wp;
        int oo = o & 31;
        float v;
        if (k < 32) v = 2.f*W[oo*96 + k] + 2.f*ALPHA*(W[oo*96 + k + 32] + W[oo*96 + k + 64]);
        else        v = W[oo*96 + k];
        splitb(v, &g_Wch[idx], &g_Wcl[idx]);
    }
    size_t i4 = ((size_t)blockIdx.x*256 + threadIdx.x)*4;
    float4 v = *(const float4*)&x[i4];
    uint32_t h01, l01, h23, l23;
    split_pair(v.x, v.y, h01, l01);
    split_pair(v.z, v.w, h23, l23);
    *(uint2*)&g_xh[i4] = make_uint2(h01, h23);
    *(uint2*)&g_xl[i4] = make_uint2(l01, l23);
}

// ============================================================
// K4: batched bf16-planar GEMM (y-stage). 3-slot ring, ONE barrier/chunk.
// Grid (4, BC): (n,m) fastest => x slice L2-hot across the 4 sibling CTAs.
// ============================================================
struct TGB {
    static const int AS = 160*40;
    static const int BS = 32*88;
    static const int STGE = 2*AS + 2*BS;          // 18432 elems / stage
    static const int SMEM = STGE*3*2;             // 110592 B (3 slots)
};

__global__ void __launch_bounds__(320, 2) k_bgemm_bf(
    const __nv_bfloat16* __restrict__ Ah, const __nv_bfloat16* __restrict__ Al,
    long sA, int lda,
    const __nv_bfloat16* __restrict__ Bh, const __nv_bfloat16* __restrict__ Bl,
    long sB, int ldb,
    __nv_bfloat16* __restrict__ Coh, __nv_bfloat16* __restrict__ Col,
    long sC, int ldc)
{
    extern __shared__ __nv_bfloat16 smb[];
    const int AS = TGB::AS, STGE = TGB::STGE;
    uint32_t sb = (uint32_t)__cvta_generic_to_shared(smb);

    int nm = blockIdx.x;
    int bc = blockIdx.y;
    int n0 = (nm & 1) * 80;
    int m0 = (nm >> 1) * 160;
    const __nv_bfloat16* Ahb = Ah + (size_t)bc*sA;
    const __nv_bfloat16* Alb = Al + (size_t)bc*sA;
    const __nv_bfloat16* Bhb = Bh + (size_t)bc*sB;
    const __nv_bfloat16* Blb = Bl + (size_t)bc*sB;

    int tid = threadIdx.x, lane = tid & 31, wid = tid >> 5;
    int wmi = wid % 5, wni = wid / 5;
    int m0w = wmi*32, n0w = wni*40;
    int g = lane >> 2, t = lane & 3;

    float acc[2][5][4] = {};

    auto stage = [&](int kt, int st) {
        uint32_t base = sb + (uint32_t)(st*STGE)*2;
        #pragma unroll
        for (int i = 0; i < 4; i++) {
            int s = tid + i*320;
            int pl = s >= 640; int ss = s - pl*640;
            int m = ss >> 2, kc = (ss & 3)*8;
            const __nv_bfloat16* src = (pl ? Alb : Ahb) + (size_t)(m0+m)*lda + kt + kc;
            cp16(base + (uint32_t)(pl*AS + m*40 + kc)*2, src);
        }
        #pragma unroll
        for (int i = 0; i < 2; i++) {
            int s = tid + i*320;
            int pl = s >= 320; int ss = s - pl*320;
            int k = ss/10, nc = (ss%10)*8;
            const __nv_bfloat16* src = (pl ? Blb : Bhb) + (size_t)(kt+k)*ldb + n0 + nc;
            cp16(base + (uint32_t)(2*AS + pl*TGB::BS + k*88 + nc)*2, src);
        }
        CP_COMMIT();
    };

    stage(0, 0);
    stage(32, 1);
    #pragma unroll
    for (int it = 0; it < 5; it++) {
        if (it < 4) cp_wait<1>(); else cp_wait<0>();
        __syncthreads();
        if (it + 2 < 5) stage((it+2)*32, (it+2)%3);   // safe: writes slot (it+2)%3, readers on it%3
        uint32_t sAh = sb + (uint32_t)((it%3)*STGE)*2;
        uint32_t sAl = sAh + (uint32_t)AS*2;
        uint32_t sBh = sAh + (uint32_t)(2*AS)*2;
        uint32_t sBl = sBh + (uint32_t)TGB::BS*2;
        #pragma unroll
        for (int kk = 0; kk < 32; kk += 16) {
            uint32_t Afh[2][4], Afl[2][4];
            #pragma unroll
            for (int mt = 0; mt < 2; mt++) {
                uint32_t off = (uint32_t)(((m0w + mt*16 + (lane&15))*40
                                           + kk + ((lane>>4)<<3)) << 1);
                ldsm4(Afh[mt], sAh + off);
                ldsm4(Afl[mt], sAl + off);
            }
            uint32_t Bfh[5][2], Bfl[5][2];
            int rB = kk + (lane&7) + (lane&8);
            #pragma unroll
            for (int ntp = 0; ntp < 2; ntp++) {
                uint32_t off = (uint32_t)((rB*88 + n0w + ntp*16 + ((lane>>4)<<3)) << 1);
                uint32_t rh[4], rl[4];
                ldsm4t(rh, sBh + off);
                ldsm4t(rl, sBl + off);
                Bfh[2*ntp][0]=rh[0]; Bfh[2*ntp][1]=rh[1]; Bfh[2*ntp+1][0]=rh[2]; Bfh[2*ntp+1][1]=rh[3];
                Bfl[2*ntp][0]=rl[0]; Bfl[2*ntp][1]=rl[1]; Bfl[2*ntp+1][0]=rl[2]; Bfl[2*ntp+1][1]=rl[3];
            }
            {
                uint32_t off = (uint32_t)((rB*88 + n0w + 32) << 1);
                ldsm2t(Bfh[4], sBh + off);
                ldsm2t(Bfl[4], sBl + off);
            }
            #pragma unroll
            for (int nt = 0; nt < 5; nt++)
            #pragma unroll
            for (int mt = 0; mt < 2; mt++) {
                mmabf(acc[mt][nt], Afh[mt], Bfh[nt]);
                mmabf(acc[mt][nt], Afh[mt], Bfl[nt]);
                mmabf(acc[mt][nt], Afl[mt], Bfh[nt]);
            }
        }
    }
    #pragma unroll
    for (int mt = 0; mt < 2; mt++) {
        int r0 = m0 + m0w + mt*16 + g;
        #pragma unroll
        for (int nt = 0; nt < 5; nt++) {
            int c0 = n0 + n0w + nt*8 + 2*t;
            __nv_bfloat16* Ch = Coh + (size_t)bc*sC;
            __nv_bfloat16* Cl = Col + (size_t)bc*sC;
            uint32_t wh, wl;
            split_pair(acc[mt][nt][0], acc[mt][nt][1], wh, wl);
            *(uint32_t*)&Ch[(size_t)r0*ldc + c0] = wh;
            *(uint32_t*)&Cl[(size_t)r0*ldc + c0] = wl;
            split_pair(acc[mt][nt][2], acc[mt][nt][3], wh, wl);
            *(uint32_t*)&Ch[(size_t)(r0+8)*ldc + c0] = wh;
            *(uint32_t*)&Cl[(size_t)(r0+8)*ldc + c0] = wl;
        }
    }
}

// ============================================================
// K5: channel mix. 3 chunks ALL staged up-front (3 slots), one barrier/chunk.
// ============================================================
#define MIXB_AS (64*40)
#define MIXB_BS (32*168)
#define MIXB_STGE (2*MIXB_AS + 2*MIXB_BS)
#define MIXB_SMEM (MIXB_STGE*3*2)

__global__ void __launch_bounds__(320, 2) k_mix_bf(
    const float* __restrict__ be, const float* __restrict__ bp)
{
    extern __shared__ __nv_bfloat16 smb[];
    uint32_t sb = (uint32_t)__cvta_generic_to_shared(smb);
    int b  = blockIdx.y;
    int p0 = blockIdx.x * 160;
    int tid = threadIdx.x, lane = tid & 31, wid = tid >> 5;
    int wmi = wid & 1, wni = wid >> 1;
    int m0w = wmi*32, n0w = wni*32;
    int g = lane >> 2, t = lane & 3;

    float acc[2][4][4] = {};

    auto stage = [&](int ktc, int st) {
        uint32_t base = sb + (uint32_t)(st*MIXB_STGE)*2;
        #pragma unroll
        for (int i = 0; i < 2; i++) {
            int s = tid + i*320;
            if (s < 512) {
                int pl = s >= 256; int ss = s & 255;
                int m = ss >> 2, kc = (ss & 3)*8;
                const __nv_bfloat16* src = (pl ? g_Wcl : g_Wch) + m*96 + ktc + kc;
                cp16(base + (uint32_t)(pl*MIXB_AS + m*40 + kc)*2, src);
            }
        }
        #pragma unroll
        for (int i = 0; i < 4; i++) {
            int s = tid + i*320;
            int pl = s >= 640; int ss = s - pl*640;
            int k = ss/20, mc = (ss%20)*8;
            int kg = ktc + k;
            int c = kg & 31;
            const __nv_bfloat16* src;
            if (pl) {
                if (kg < 32)      src = g_xl + ((size_t)b*32 + c)*NL;
                else if (kg < 64) src = g_yl + ((size_t)b*32 + c)*(2*NL);
                else              src = g_yl + ((size_t)b*32 + c)*(2*NL) + NL;
            } else {
                if (kg < 32)      src = g_xh + ((size_t)b*32 + c)*NL;
                else if (kg < 64) src = g_yh + ((size_t)b*32 + c)*(2*NL);
                else              src = g_yh + ((size_t)b*32 + c)*(2*NL) + NL;
            }
            cp16(base + (uint32_t)(2*MIXB_AS + pl*MIXB_BS + k*168 + mc)*2, src + p0 + mc);
        }
        CP_COMMIT();
    };

    stage(0, 0);
    stage(32, 1);
    stage(64, 2);
    #pragma unroll
    for (int it = 0; it < 3; it++) {
        if (it == 0)      cp_wait<2>();
        else if (it == 1) cp_wait<1>();
        else              cp_wait<0>();
        __syncthreads();
        uint32_t sAh = sb + (uint32_t)(it*MIXB_STGE)*2;
        uint32_t sAl = sAh + (uint32_t)MIXB_AS*2;
        uint32_t sBh = sAh + (uint32_t)(2*MIXB_AS)*2;
        uint32_t sBl = sBh + (uint32_t)MIXB_BS*2;
        #pragma unroll
        for (int kk = 0; kk < 32; kk += 16) {
            uint32_t Afh[2][4], Afl[2][4];
            #pragma unroll
            for (int mt = 0; mt < 2; mt++) {
                uint32_t off = (uint32_t)(((m0w + mt*16 + (lane&15))*40
                                           + kk + ((lane>>4)<<3)) << 1);
                ldsm4(Afh[mt], sAh + off);
                ldsm4(Afl[mt], sAl + off);
            }
            uint32_t Bfh[4][2], Bfl[4][2];
            int rB = kk + (lane&7) + (lane&8);
            #pragma unroll
            for (int ntp = 0; ntp < 2; ntp++) {
                uint32_t off = (uint32_t)((rB*168 + n0w + ntp*16 + ((lane>>4)<<3)) << 1);
                uint32_t rh[4], rl[4];
                ldsm4t(rh, sBh + off);
                ldsm4t(rl, sBl + off);
                Bfh[2*ntp][0]=rh[0]; Bfh[2*ntp][1]=rh[1]; Bfh[2*ntp+1][0]=rh[2]; Bfh[2*ntp+1][1]=rh[3];
                Bfl[2*ntp][0]=rl[0]; Bfl[2*ntp][1]=rl[1]; Bfl[2*ntp+1][0]=rl[2]; Bfl[2*ntp+1][1]=rl[3];
            }
            #pragma unroll
            for (int nt = 0; nt < 4; nt++)
            #pragma unroll
            for (int mt = 0; mt < 2; mt++) {
                mmabf(acc[mt][nt], Afh[mt], Bfh[nt]);
                mmabf(acc[mt][nt], Afh[mt], Bfl[nt]);
                mmabf(acc[mt][nt], Afl[mt], Bfh[nt]);
            }
        }
    }
    #pragma unroll
    for (int mt = 0; mt < 2; mt++) {
        #pragma unroll
        for (int rr = 0; rr < 2; rr++) {
            int o = m0w + mt*16 + g + rr*8;
            float bias = 2.f * ((o < 32) ? be[o] : bp[o-32]);
            int oo = o & 31;
            size_t base = ((size_t)b*32 + oo)*NL + p0;
            #pragma unroll
            for (int nt = 0; nt < 4; nt++) {
                int c0 = n0w + nt*8 + 2*t;
                float u0 = acc[mt][nt][rr*2+0] + bias;
                float u1 = acc[mt][nt][rr*2+1] + bias;
                if (o < 32) {
                    uint32_t wh, wl;
                    split_pair(u0, u1, wh, wl);
                    *(uint32_t*)&g_eh[base + c0] = wh;
                    *(uint32_t*)&g_el[base + c0] = wl;
                } else {
                    *(float2*)&g_pool[base + c0] = make_float2(u0, u1);
                }
            }
        }
    }
}

// ============================================================
// K6: softmax over node axis; split bf16 planar output
// ============================================================
#define SMAX_SMEM (160*161*4)
__global__ void k_softmax3() {
    extern __shared__ float sp[];
    int bc = blockIdx.x;
    int l = threadIdx.x;
    const float* p = g_pool + (size_t)bc*NL;
    for (int n = 0; n < Ndim; n++)
        sp[n*161 + l] = p[n*Ndim + l];
    __syncthreads();
    float m = -3.4e38f, d = 0.f;
    #pragma unroll 4
    for (int n = 0; n < Ndim; n++) {
        float v = sp[n*161 + l];
        float m2 = fmaxf(m, v);
        d = d * __expf(m - m2) + __expf(v - m2);
        m = m2;
    }
    float inv = 1.f / d;
    __nv_bfloat16* sh = g_sh + (size_t)bc*NL;
    __nv_bfloat16* sl = g_sl + (size_t)bc*NL;
    #pragma unroll 4
    for (int n = 0; n < Ndim; n++) {
        float v = __expf(sp[n*161 + l] - m) * inv;
        splitb(v, &sh[n*Ndim + l], &sl[n*Ndim + l]);
    }
}

// ---- shared B-fragment mma helper (80-col row) ----
__device__ __forceinline__ void frag_mma_row(
    float (&acc)[10][4], const uint32_t* Ah, const uint32_t* Al,
    uint32_t sBh, uint32_t sBl, int rB, int ldb, int n0w, int lane)
{
    #pragma unroll
    for (int ntp = 0; ntp < 5; ntp++) {
        uint32_t off = (uint32_t)((rB*ldb + n0w + ntp*16 + ((lane>>4)<<3)) << 1);
        uint32_t rh[4], rl[4];
        ldsm4t(rh, sBh + off);
        ldsm4t(rl, sBl + off);
        uint32_t bh0[2] = {rh[0], rh[1]}, bh1[2] = {rh[2], rh[3]};
        uint32_t bl0[2] = {rl[0], rl[1]}, bl1[2] = {rl[2], rl[3]};
        mmabf(acc[2*ntp],   Ah, bh0);
        mmabf(acc[2*ntp],   Ah, bl0);
        mmabf(acc[2*ntp],   Al, bh0);
        mmabf(acc[2*ntp+1], Ah, bh1);
        mmabf(acc[2*ntp+1], Ah, bl1);
        mmabf(acc[2*ntp+1], Al, bh1);
    }
}

// ============================================================
// K7a: x_new = s^T @ e.  Grid (2, BC): halves co-resident -> e L2-hit.
// s-half tile [160][88]/plane. 2 CTAs/SM. (ring-2, 2 syncs/chunk — ring-3
// doesn't fit at 2 CTAs/SM.)
// ============================================================
#define XN_SCL   14080
#define XN_RING  28160
#define XN_PL    5376
#define XN_SLOT  10752
#define XN_SMEM  (49664*2)

__global__ void __launch_bounds__(320, 2) k_xn(float* __restrict__ xnew)
{
    extern __shared__ __nv_bfloat16 smb[];
    uint32_t sb = (uint32_t)__cvta_generic_to_shared(smb);
    int h  = blockIdx.x;
    int bc = blockIdx.y;
    int tid = threadIdx.x, lane = tid & 31, wid = tid >> 5;
    int wmi = wid % 5, wni = wid / 5;
    int g = lane >> 2, t4 = lane & 3;
    int m0w = wmi*16;
    int n0w = wni*80;

    const __nv_bfloat16* sh_g = g_sh + (size_t)bc*NL + h*80;
    const __nv_bfloat16* sl_g = g_sl + (size_t)bc*NL + h*80;
    const __nv_bfloat16* eh_g = g_eh + (size_t)bc*NL;
    const __nv_bfloat16* el_g = g_el + (size_t)bc*NL;

    #pragma unroll
    for (int i = 0; i < 10; i++) {
        int s = tid + i*320;
        int pl = s >= 1600; int ss = s - pl*1600;
        int r = ss/10, c8 = (ss%10)*8;
        const __nv_bfloat16* src = (pl ? sl_g : sh_g) + r*160 + c8;
        cp16(sb + (uint32_t)((pl ? XN_SCL : 0) + r*88 + c8)*2, src);
    }
    CP_COMMIT();

    auto stage_e = [&](int ch, int slot) {
        uint32_t base = sb + (uint32_t)(XN_RING + slot*XN_SLOT)*2;
        #pragma unroll
        for (int i = 0; i < 4; i++) {
            int s = tid + i*320;
            int pl = s >= 640; int ss = s - pl*640;
            int r = ss/20, c8 = (ss%20)*8;
            const __nv_bfloat16* src = (pl ? el_g : eh_g) + (ch*32 + r)*160 + c8;
            cp16(base + (uint32_t)(pl*XN_PL + r*168 + c8)*2, src);
        }
        CP_COMMIT();
    };

    float acc[10][4];
    #pragma unroll
    for (int i = 0; i < 10; i++)
        acc[i][0] = acc[i][1] = acc[i][2] = acc[i][3] = 0.f;

    stage_e(0, 0);
    for (int ch = 0; ch < 5; ch++) {
        if (ch + 1 < 5) { stage_e(ch+1, (ch+1)&1); cp_wait<1>(); }
        else            { cp_wait<0>(); }
        __syncthreads();
        uint32_t stb  = sb + (uint32_t)(XN_RING + (ch&1)*XN_SLOT)*2;
        uint32_t stbl = stb + (uint32_t)XN_PL*2;
        #pragma unroll
        for (int kk = 0; kk < 32; kk += 16) {
            int kg = ch*32 + kk;
            uint32_t Ah[4], Al[4];
            uint32_t offA = (uint32_t)(((kg + (lane&7) + ((lane>>4)<<3))*88
                                        + m0w + (lane&8)) << 1);
            ldsm4t(Ah, sb + offA);
            ldsm4t(Al, sb + (uint32_t)(XN_SCL*2) + offA);
            int rB = kk + (lane&7) + (lane&8);
            frag_mma_row(acc, Ah, Al, stb, stbl, rB, 168, n0w, lane);
        }
        __syncthreads();
    }
    {
        float* X = xnew + (size_t)bc*NL;
        int r0 = h*80 + m0w + g;
        #pragma unroll
        for (int nt = 0; nt < 10; nt++) {
            int c0 = n0w + nt*8 + 2*t4;
            *(float2*)&X[(size_t)r0*160 + c0]     = make_float2(acc[nt][0], acc[nt][1]);
            *(float2*)&X[(size_t)(r0+8)*160 + c0] = make_float2(acc[nt][2], acc[nt][3]);
        }
    }
}

// ============================================================
// K7b: t = s @ a ; a_new = t @ s.  One CTA per bc, full 160 rows.
// ============================================================
#define AN_SL  26880
#define AN_TH  53760
#define AN_TL  80640
#define AN_SMEM (107520*2)

__global__ void __launch_bounds__(320, 1) k_an(float* __restrict__ anew)
{
    extern __shared__ __nv_bfloat16 smb[];
    uint32_t sb = (uint32_t)__cvta_generic_to_shared(smb);
    int bc = blockIdx.x;
    int tid = threadIdx.x, lane = tid & 31, wid = tid >> 5;
    int wmi = wid % 5, wni = wid / 5;
    int g = lane >> 2, t4 = lane & 3;
    int n0w = wni*80;

    const __nv_bfloat16* sh_g = g_sh + (size_t)bc*NL;
    const __nv_bfloat16* sl_g = g_sl + (size_t)bc*NL;

    auto stage_ch = [&](int ch) {
        #pragma unroll
        for (int i = 0; i < 4; i++) {
            int s = tid + i*320;
            int pl = s >= 640; int ss = s - pl*640;
            int r = ss >> 2, c8 = (ss & 3)*8;
            const __nv_bfloat16* src = (pl ? sl_g : sh_g) + r*160 + ch*32 + c8;
            cp16(sb + (uint32_t)((pl ? AN_SL : 0) + r*168 + ch*32 + c8)*2, src);
        }
        #pragma unroll
        for (int i = 0; i < 4; i++) {
            int s = tid + i*320;
            int pl = s >= 640; int ss = s - pl*640;
            int r = ss/20, c8 = (ss%20)*8;
            const __nv_bfloat16* src = (pl ? g_al : g_ah) + (ch*32 + r)*160 + c8;
            cp16(sb + (uint32_t)((pl ? AN_TL : AN_TH) + (ch*32 + r)*168 + c8)*2, src);
        }
        CP_COMMIT();
    };

    stage_ch(0); stage_ch(1); stage_ch(2); stage_ch(3); stage_ch(4);

    float acc[2][10][4];
    #pragma unroll
    for (int mt = 0; mt < 2; mt++)
    #pragma unroll
    for (int i = 0; i < 10; i++)
        acc[mt][i][0] = acc[mt][i][1] = acc[mt][i][2] = acc[mt][i][3] = 0.f;

    // ---- phase 1: t = s @ a ----
    #pragma unroll
    for (int ch = 0; ch < 5; ch++) {
        switch (ch) {
            case 0: cp_wait<4>(); break;
            case 1: cp_wait<3>(); break;
            case 2: cp_wait<2>(); break;
            case 3: cp_wait<1>(); break;
            default: cp_wait<0>(); break;
        }
        __syncthreads();
        #pragma unroll
        for (int kk = 0; kk < 32; kk += 16) {
            int kg = ch*32 + kk;
            uint32_t Ah[2][4], Al[2][4];
            #pragma unroll
            for (int mt = 0; mt < 2; mt++) {
                uint32_t offA = (uint32_t)(((wmi*32 + mt*16 + (lane&15))*168
                                            + kg + ((lane>>4)<<3)) << 1);
                ldsm4(Ah[mt], sb + offA);
                ldsm4(Al[mt], sb + (uint32_t)(AN_SL*2) + offA);
            }
            int rB = kg + (lane&7) + (lane&8);
            #pragma unroll
            for (int ntp = 0; ntp < 5; ntp++) {
                uint32_t off = (uint32_t)((rB*168 + n0w + ntp*16 + ((lane>>4)<<3)) << 1);
                uint32_t rh[4], rl[4];
                ldsm4t(rh, sb + (uint32_t)(AN_TH*2) + off);
                ldsm4t(rl, sb + (uint32_t)(AN_TL*2) + off);
                uint32_t bh0[2] = {rh[0], rh[1]}, bh1[2] = {rh[2], rh[3]};
                uint32_t bl0[2] = {rl[0], rl[1]}, bl1[2] = {rl[2], rl[3]};
                #pragma unroll
                for (int mt = 0; mt < 2; mt++) {
                    mmabf(acc[mt][2*ntp],   Ah[mt], bh0);
                    mmabf(acc[mt][2*ntp],   Ah[mt], bl0);
                    mmabf(acc[mt][2*ntp],   Al[mt], bh0);
                    mmabf(acc[mt][2*ntp+1], Ah[mt], bh1);
                    mmabf(acc[mt][2*ntp+1], Ah[mt], bl1);
                    mmabf(acc[mt][2*ntp+1], Al[mt], bh1);
                }
            }
        }
    }
    __syncthreads();

    // ---- t -> smem planes (overwrite a region) ----
    #pragma unroll
    for (int mt = 0; mt < 2; mt++) {
        int r0l = wmi*32 + mt*16 + g;
        #pragma unroll
        for (int nt = 0; nt < 10; nt++) {
            int c0 = n0w + nt*8 + 2*t4;
            uint32_t wh, wl;
            split_pair(acc[mt][nt][0], acc[mt][nt][1], wh, wl);
            *(uint32_t*)(smb + AN_TH + r0l*168 + c0) = wh;
            *(uint32_t*)(smb + AN_TL + r0l*168 + c0) = wl;
            split_pair(acc[mt][nt][2], acc[mt][nt][3], wh, wl);
            *(uint32_t*)(smb + AN_TH + (r0l+8)*168 + c0) = wh;
            *(uint32_t*)(smb + AN_TL + (r0l+8)*168 + c0) = wl;
        }
    }
    __syncthreads();

    // ---- phase 2: a_new = t @ s (all smem) ----
    #pragma unroll
    for (int mt = 0; mt < 2; mt++)
    #pragma unroll
    for (int i = 0; i < 10; i++)
        acc[mt][i][0] = acc[mt][i][1] = acc[mt][i][2] = acc[mt][i][3] = 0.f;
    #pragma unroll
    for (int k16 = 0; k16 < 10; k16++) {
        int kg = k16*16;
        uint32_t Ah[2][4], Al[2][4];
        #pragma unroll
        for (int mt = 0; mt < 2; mt++) {
            uint32_t offA = (uint32_t)(((wmi*32 + mt*16 + (lane&15))*168
                                        + kg + ((lane>>4)<<3)) << 1);
            ldsm4(Ah[mt], sb + (uint32_t)(AN_TH*2) + offA);
            ldsm4(Al[mt], sb + (uint32_t)(AN_TL*2) + offA);
        }
        int rB = kg + (lane&7) + (lane&8);
        #pragma unroll
        for (int ntp = 0; ntp < 5; ntp++) {
            uint32_t off = (uint32_t)((rB*168 + n0w + ntp*16 + ((lane>>4)<<3)) << 1);
            uint32_t rh[4], rl[4];
            ldsm4t(rh, sb + off);
            ldsm4t(rl, sb + (uint32_t)(AN_SL*2) + off);
            uint32_t bh0[2] = {rh[0], rh[1]}, bh1[2] = {rh[2], rh[3]};
            uint32_t bl0[2] = {rl[0], rl[1]}, bl1[2] = {rl[2], rl[3]};
            #pragma unroll
            for (int mt = 0; mt < 2; mt++) {
                mmabf(acc[mt][2*ntp],   Ah[mt], bh0);
                mmabf(acc[mt][2*ntp],   Ah[mt], bl0);
                mmabf(acc[mt][2*ntp],   Al[mt], bh0);
                mmabf(acc[mt][2*ntp+1], Ah[mt], bh1);
                mmabf(acc[mt][2*ntp+1], Ah[mt], bl1);
                mmabf(acc[mt][2*ntp+1], Al[mt], bh1);
            }
        }
    }
    {
        float* Aout = anew + (size_t)bc*NL;
        #pragma unroll
        for (int mt = 0; mt < 2; mt++) {
            int r0 = wmi*32 + mt*16 + g;
            #pragma unroll
            for (int nt = 0; nt < 10; nt++) {
                int c0 = n0w + nt*8 + 2*t4;
                *(float2*)&Aout[(size_t)r0*160 + c0] =
                    make_float2(acc[mt][nt][0], acc[mt][nt][1]);
                *(float2*)&Aout[(size_t)(r0+8)*160 + c0] =
                    make_float2(acc[mt][nt][2], acc[mt][nt][3]);
            }
        }
    }
}

// ============================================================
extern "C" void kernel_launch(void* const* d_in, const int* in_sizes, int n_in,
                              void* d_out, int out_size) {
    const float* x  = (const float*)d_in[0];
    const float* a  = (const float*)d_in[1];
    const float* We = (const float*)d_in[2];
    const float* be = (const float*)d_in[3];
    const float* Wp = (const float*)d_in[4];
    const float* bp = (const float*)d_in[5];
    float* out  = (float*)d_out;
    float* xnew = out;
    float* anew = out + (size_t)BC*NL;

    void *pMsh, *pMsl, *pxh, *pxl, *pyh, *pyl;
    cudaGetSymbolAddress(&pMsh, g_Msh); cudaGetSymbolAddress(&pMsl, g_Msl);
    cudaGetSymbolAddress(&pxh,  g_xh);  cudaGetSymbolAddress(&pxl,  g_xl);
    cudaGetSymbolAddress(&pyh,  g_yh);  cudaGetSymbolAddress(&pyl,  g_yl);

    cudaFuncSetAttribute((const void*)k_bgemm_bf,
        cudaFuncAttributeMaxDynamicSharedMemorySize, TGB::SMEM);
    cudaFuncSetAttribute((const void*)k_mix_bf,
        cudaFuncAttributeMaxDynamicSharedMemorySize, MIXB_SMEM);
    cudaFuncSetAttribute((const void*)k_softmax3,
        cudaFuncAttributeMaxDynamicSharedMemorySize, SMAX_SMEM);
    cudaFuncSetAttribute((const void*)k_xn,
        cudaFuncAttributeMaxDynamicSharedMemorySize, XN_SMEM);
    cudaFuncSetAttribute((const void*)k_an,
        cudaFuncAttributeMaxDynamicSharedMemorySize, AN_SMEM);

    k_norm_adj<<<Ndim, Ndim>>>(a);
    k_prep<<<dim3(5, 5), 64>>>();
    k_xsplit<<<(int)(((size_t)BC*NL)/1024), 256>>>(x, We, Wp);

    // ystack = Ms @ x : (n,m) fastest for x L2 reuse
    k_bgemm_bf<<<dim3(4, BC), 320, TGB::SMEM>>>(
        (const __nv_bfloat16*)pMsh, (const __nv_bfloat16*)pMsl, 0, Ndim,
        (const __nv_bfloat16*)pxh,  (const __nv_bfloat16*)pxl,  NL, Ndim,
        (__nv_bfloat16*)pyh, (__nv_bfloat16*)pyl, 2*NL, Ndim);

    // channel mix -> embed (split planes), pool (fp32)
    k_mix_bf<<<dim3(NL/160, Bdim), 320, MIXB_SMEM>>>(be, bp);

    k_softmax3<<<BC, Ndim, SMAX_SMEM>>>();

    // x_new = s^T @ e  (halves co-resident; 2 CTAs/SM)
    k_xn<<<dim3(2, BC), 320, XN_SMEM>>>(xnew);

    // t = s @ a ; a_new = t @ s  (smem-resident)
    k_an<<<BC, 320, AN_SMEM>>>(anew);
}